// round 10
// baseline (speedup 1.0000x reference)
#include <cuda_runtime.h>
#include <cuda_fp16.h>
#include <cstdint>
#include <float.h>

// Problem constants
#define BB 4
#define LL 4096
#define DHQ 1024
#define TTQ 1024
#define DGQ 768
#define PPQ 256

// Scratch (__device__ globals; no cudaMalloc allowed)
__device__ float g_K[(size_t)BB * LL * PPQ];   // 16 MB
__device__ float g_Q[(size_t)BB * TTQ * PPQ];  //  4 MB
__device__ float g_S[(size_t)BB * TTQ * LL];   // 64 MB

// ---------------------------------------------------------------------------
// helpers
// ---------------------------------------------------------------------------
__device__ __forceinline__ void mma_fp16(float* d, const uint32_t* a, const uint32_t* b) {
    asm volatile(
        "mma.sync.aligned.m16n8k16.row.col.f32.f16.f16.f32 "
        "{%0,%1,%2,%3}, {%4,%5,%6,%7}, {%8,%9}, {%0,%1,%2,%3};"
        : "+f"(d[0]), "+f"(d[1]), "+f"(d[2]), "+f"(d[3])
        : "r"(a[0]), "r"(a[1]), "r"(a[2]), "r"(a[3]), "r"(b[0]), "r"(b[1]));
}

__device__ __forceinline__ uint32_t h2_u32(__half2 h) {
    return *reinterpret_cast<uint32_t*>(&h);
}

// Split float pair -> (hi half2, lo half2). fp16 products are exact in fp32.
__device__ __forceinline__ void split2(float x, float y, uint32_t& hi, uint32_t& lo) {
    __half2 h = __floats2half2_rn(x, y);
    float2 hb = __half22float2(h);
    __half2 l = __floats2half2_rn(x - hb.x, y - hb.y);
    hi = h2_u32(h);
    lo = h2_u32(l);
}

// ---------------------------------------------------------------------------
// fp16 split tensor-core GEMM: C[M,N] = scale * A[M,K] * op(B)
//   BT=true : B is [N,K] row-major (NT);  BT=false: B is [K,N] row-major (NN)
//   TERMS=3: aH*bH + aH*bL + aL*bH  (rel err ~2^-22 class)
//   TERMS=2: aH*(bH + bL)           (A effectively fp16)
//   TERMS=1: aH*bH                  (both fp16; err ~2^-12 RMS)
// Block tile 128x128, BK=32, 256 threads (8 warps, 64x32 warp tiles).
// SMEM stages hold PRE-SPLIT half data:
//   A_hi [128][40] halves @0, A_lo @5120
//   NT B: B_hi [128][40] @10240, B_lo @15360
//   NN B: B_hi [32][136] @10240, B_lo @14592
// Stage = 20480 halves = 40960 B; 2 stages.
// Optional per-column int32 mask (logits): nonzero -> -FLT_MAX.
// ---------------------------------------------------------------------------
#define STAGE_H 20480
#define SMEM_GEMM (2 * STAGE_H * 2)   // 81920 bytes

template <bool BT, int TERMS>
__global__ __launch_bounds__(256)
void fp16x3_gemm(const float* __restrict__ A, const float* __restrict__ B,
                 float* __restrict__ C,
                 int K, long lda, long ldb, long ldc,
                 long sA, long sB, long sC,
                 float scale, const int* __restrict__ mask, long maskStride)
{
    extern __shared__ __align__(16) uint16_t smh[];

    const int tid  = threadIdx.x;
    const int wid  = tid >> 5;
    const int lane = tid & 31;
    const int grp  = lane >> 2;       // 0..7
    const int tig  = lane & 3;        // 0..3
    const int wm   = (wid & 1) * 64;  // warp m offset
    const int wn   = (wid >> 1) * 32; // warp n offset

    const int bz = blockIdx.z;
    A += (long)bz * sA;
    B += (long)bz * sB;
    C += (long)bz * sC;
    if (mask) mask += (long)bz * maskStride;

    const long row0 = (long)blockIdx.y * 128;
    const long col0 = (long)blockIdx.x * 128;

    const int nIter = K >> 5;   // BK = 32

    float4 rA[4], rB[4];

    auto load_tile = [&](int it) {
        const float* pA = A + row0 * lda + (long)it * 32;
#pragma unroll
        for (int p = 0; p < 4; ++p) {
            const int f = p * 256 + tid;
            rA[p] = *reinterpret_cast<const float4*>(pA + (long)(f >> 3) * lda + (f & 7) * 4);
        }
        if (BT) {
            const float* pB = B + col0 * ldb + (long)it * 32;
#pragma unroll
            for (int p = 0; p < 4; ++p) {
                const int f = p * 256 + tid;
                rB[p] = *reinterpret_cast<const float4*>(pB + (long)(f >> 3) * ldb + (f & 7) * 4);
            }
        } else {
            const float* pB = B + (long)it * 32 * ldb + col0;
#pragma unroll
            for (int p = 0; p < 4; ++p) {
                const int f = p * 256 + tid;
                rB[p] = *reinterpret_cast<const float4*>(pB + (long)(f >> 5) * ldb + (f & 31) * 4);
            }
        }
    };

    auto store_tile = [&](uint16_t* st) {
#pragma unroll
        for (int p = 0; p < 4; ++p) {
            const int f = p * 256 + tid;
            {   // A: [m][40] halves, hi @0, lo @5120
                const int m = f >> 3, kc = (f & 7) * 4;
                float4 v = rA[p];
                uint32_t h0, l0, h1, l1;
                split2(v.x, v.y, h0, l0);
                split2(v.z, v.w, h1, l1);
                *reinterpret_cast<uint2*>(st + m * 40 + kc) = make_uint2(h0, h1);
                if (TERMS == 3)
                    *reinterpret_cast<uint2*>(st + 5120 + m * 40 + kc) = make_uint2(l0, l1);
            }
            if (BT) {   // B: [n][40] halves, hi @10240, lo @15360
                const int n = f >> 3, kc = (f & 7) * 4;
                float4 v = rB[p];
                uint32_t h0, l0, h1, l1;
                split2(v.x, v.y, h0, l0);
                split2(v.z, v.w, h1, l1);
                *reinterpret_cast<uint2*>(st + 10240 + n * 40 + kc) = make_uint2(h0, h1);
                if (TERMS >= 2)
                    *reinterpret_cast<uint2*>(st + 15360 + n * 40 + kc) = make_uint2(l0, l1);
            } else {    // B: [k][136] halves, hi @10240, lo @14592
                const int k = f >> 5, nc = (f & 31) * 4;
                float4 v = rB[p];
                uint32_t h0, l0, h1, l1;
                split2(v.x, v.y, h0, l0);
                split2(v.z, v.w, h1, l1);
                *reinterpret_cast<uint2*>(st + 10240 + k * 136 + nc) = make_uint2(h0, h1);
                if (TERMS >= 2)
                    *reinterpret_cast<uint2*>(st + 14592 + k * 136 + nc) = make_uint2(l0, l1);
            }
        }
    };

    float acc[4][4][4];
#pragma unroll
    for (int i = 0; i < 4; ++i)
#pragma unroll
        for (int j = 0; j < 4; ++j)
#pragma unroll
            for (int r = 0; r < 4; ++r) acc[i][j][r] = 0.0f;

    load_tile(0);
    store_tile(smh);
    __syncthreads();

    for (int it = 0; it < nIter; ++it) {
        const bool more = (it + 1 < nIter);
        if (more) load_tile(it + 1);

        const uint16_t* st = smh + (it & 1) * STAGE_H;
        const uint32_t* sw = reinterpret_cast<const uint32_t*>(st);

#pragma unroll
        for (int ks = 0; ks < 2; ++ks) {
            uint32_t aH[4][4], aL[4][4], bH[4][2], bL[4][2];
#pragma unroll
            for (int i = 0; i < 4; ++i) {
                const int r  = wm + i * 16 + grp;
                const int w0 = r * 20 + tig + 8 * ks;
                const int w1 = (r + 8) * 20 + tig + 8 * ks;
                aH[i][0] = sw[w0];     aH[i][1] = sw[w1];
                aH[i][2] = sw[w0 + 4]; aH[i][3] = sw[w1 + 4];
                if (TERMS == 3) {
                    aL[i][0] = sw[2560 + w0];     aL[i][1] = sw[2560 + w1];
                    aL[i][2] = sw[2560 + w0 + 4]; aL[i][3] = sw[2560 + w1 + 4];
                }
            }
#pragma unroll
            for (int j = 0; j < 4; ++j) {
                const int n = wn + j * 8 + grp;
                if (BT) {
                    const int w0 = 5120 + n * 20 + tig + 8 * ks;
                    bH[j][0] = sw[w0];        bH[j][1] = sw[w0 + 4];
                    if (TERMS >= 2) {
                        bL[j][0] = sw[2560 + w0]; bL[j][1] = sw[2560 + w0 + 4];
                    }
                } else {
                    const int kb = 2 * tig + 16 * ks;
                    const uint16_t* bh = st + 10240;
                    const uint16_t* bl = st + 14592;
                    bH[j][0] = (uint32_t)bh[kb * 136 + n]       | ((uint32_t)bh[(kb + 1) * 136 + n] << 16);
                    bH[j][1] = (uint32_t)bh[(kb + 8) * 136 + n] | ((uint32_t)bh[(kb + 9) * 136 + n] << 16);
                    if (TERMS >= 2) {
                        bL[j][0] = (uint32_t)bl[kb * 136 + n]       | ((uint32_t)bl[(kb + 1) * 136 + n] << 16);
                        bL[j][1] = (uint32_t)bl[(kb + 8) * 136 + n] | ((uint32_t)bl[(kb + 9) * 136 + n] << 16);
                    }
                }
            }
            // Separate sweeps: dependent MMAs on one accumulator are 16 apart.
#pragma unroll
            for (int i = 0; i < 4; ++i)
#pragma unroll
                for (int j = 0; j < 4; ++j)
                    mma_fp16(acc[i][j], aH[i], bH[j]);
            if (TERMS >= 2) {
#pragma unroll
                for (int i = 0; i < 4; ++i)
#pragma unroll
                    for (int j = 0; j < 4; ++j)
                        mma_fp16(acc[i][j], aH[i], bL[j]);
            }
            if (TERMS == 3) {
#pragma unroll
                for (int i = 0; i < 4; ++i)
#pragma unroll
                    for (int j = 0; j < 4; ++j)
                        mma_fp16(acc[i][j], aL[i], bH[j]);
            }
        }

        if (more) store_tile(smh + ((it + 1) & 1) * STAGE_H);
        __syncthreads();
    }

    // Epilogue: register -> gmem (float2 per row-pair), scale + mask
#pragma unroll
    for (int i = 0; i < 4; ++i) {
        const long r0 = row0 + wm + i * 16 + grp;
#pragma unroll
        for (int j = 0; j < 4; ++j) {
            const long gc = col0 + wn + j * 8 + tig * 2;
            float x0 = acc[i][j][0] * scale, x1 = acc[i][j][1] * scale;
            float y0 = acc[i][j][2] * scale, y1 = acc[i][j][3] * scale;
            if (mask) {
                const bool m0 = mask[gc] != 0, m1 = mask[gc + 1] != 0;
                if (m0) { x0 = -FLT_MAX; y0 = -FLT_MAX; }
                if (m1) { x1 = -FLT_MAX; y1 = -FLT_MAX; }
            }
            *reinterpret_cast<float2*>(C + r0 * ldc + gc)       = make_float2(x0, x1);
            *reinterpret_cast<float2*>(C + (r0 + 8) * ldc + gc) = make_float2(y0, y1);
        }
    }
}

// ---------------------------------------------------------------------------
// Row softmax over LL (float4 I/O)
// ---------------------------------------------------------------------------
__global__ __launch_bounds__(256)
void softmax_kernel(float* __restrict__ S)
{
    __shared__ float4 buf[LL / 4];
    __shared__ float red[256];

    const int tid = threadIdx.x;
    float4* p = reinterpret_cast<float4*>(S + (long)blockIdx.x * LL);

    float m = -FLT_MAX;
#pragma unroll
    for (int i = tid; i < LL / 4; i += 256) {
        float4 v = p[i];
        buf[i] = v;
        m = fmaxf(m, fmaxf(fmaxf(v.x, v.y), fmaxf(v.z, v.w)));
    }
    red[tid] = m;
    __syncthreads();
    for (int s = 128; s > 0; s >>= 1) {
        if (tid < s) red[tid] = fmaxf(red[tid], red[tid + s]);
        __syncthreads();
    }
    m = red[0];
    __syncthreads();

    float sum = 0.0f;
#pragma unroll
    for (int i = tid; i < LL / 4; i += 256) {
        float4 v = buf[i];
        v.x = __expf(v.x - m); v.y = __expf(v.y - m);
        v.z = __expf(v.z - m); v.w = __expf(v.w - m);
        buf[i] = v;
        sum += v.x + v.y + v.z + v.w;
    }
    red[tid] = sum;
    __syncthreads();
    for (int s = 128; s > 0; s >>= 1) {
        if (tid < s) red[tid] += red[tid + s];
        __syncthreads();
    }
    const float inv = 1.0f / red[0];

#pragma unroll
    for (int i = tid; i < LL / 4; i += 256) {
        float4 v = buf[i];
        v.x *= inv; v.y *= inv; v.z *= inv; v.w *= inv;
        p[i] = v;
    }
}

// ---------------------------------------------------------------------------
// Launch. Inputs: H [B,L,DH] f32, G [B,T,DG] f32, mask [B,L] int32,
// Wk_w [P,DH] f32, Wq_w [P,DG] f32. Output Z [B,T,DH] f32.
// ---------------------------------------------------------------------------
extern "C" void kernel_launch(void* const* d_in, const int* in_sizes, int n_in,
                              void* d_out, int out_size)
{
    const float* H    = (const float*)d_in[0];
    const float* G    = (const float*)d_in[1];
    const int*   mask = (const int*)d_in[2];
    const float* Wk   = (const float*)d_in[3];
    const float* Wq   = (const float*)d_in[4];
    float*       Z    = (float*)d_out;

    float *gK, *gQ, *gS;
    cudaGetSymbolAddress((void**)&gK, g_K);
    cudaGetSymbolAddress((void**)&gQ, g_Q);
    cudaGetSymbolAddress((void**)&gS, g_S);

    cudaFuncSetAttribute(fp16x3_gemm<true, 3>,
                         cudaFuncAttributeMaxDynamicSharedMemorySize, SMEM_GEMM);
    cudaFuncSetAttribute(fp16x3_gemm<false, 1>,
                         cudaFuncAttributeMaxDynamicSharedMemorySize, SMEM_GEMM);

    // 1) K = H * Wk^T : [B*L, DH] x [P, DH]^T -> [B*L, P]
    fp16x3_gemm<true, 3><<<dim3(PPQ / 128, (BB * LL) / 128, 1), 256, SMEM_GEMM>>>(
        H, Wk, gK, DHQ, DHQ, DHQ, PPQ, 0, 0, 0, 1.0f, nullptr, 0);

    // 2) Q = G * Wq^T : [B*T, DG] x [P, DG]^T -> [B*T, P]
    fp16x3_gemm<true, 3><<<dim3(PPQ / 128, (BB * TTQ) / 128, 1), 256, SMEM_GEMM>>>(
        G, Wq, gQ, DGQ, DGQ, DGQ, PPQ, 0, 0, 0, 1.0f, nullptr, 0);

    // 3) S = scale * Q * K^T (masked) : per batch [T, P] x [L, P]^T -> [T, L]
    fp16x3_gemm<true, 3><<<dim3(LL / 128, TTQ / 128, BB), 256, SMEM_GEMM>>>(
        gQ, gK, gS, PPQ, PPQ, PPQ, LL,
        (long)TTQ * PPQ, (long)LL * PPQ, (long)TTQ * LL,
        0.0625f, mask, (long)LL);

    // 4) softmax over L
    softmax_kernel<<<BB * TTQ, 256>>>(gS);

    // 5) Z = alpha * H : per batch [T, L] x [L, DH] (NN) -> [T, DH]
    //    1-term: alpha_hi * H_hi — error ~2^-12 RMS, norm-relative (weighted
    //    average: signal and noise both scale with sqrt(sum alpha^2)).
    fp16x3_gemm<false, 1><<<dim3(DHQ / 128, TTQ / 128, BB), 256, SMEM_GEMM>>>(
        gS, H, Z, LL, LL, DHQ, DHQ,
        (long)TTQ * LL, (long)LL * DHQ, (long)TTQ * DHQ,
        1.0f, nullptr, 0);
}

// round 11
// speedup vs baseline: 1.4604x; 1.4604x over previous
#include <cuda_runtime.h>
#include <cuda_fp16.h>
#include <cstdint>
#include <float.h>

// Problem constants
#define BB 4
#define LL 4096
#define DHQ 1024
#define TTQ 1024
#define DGQ 768
#define PPQ 256

// Scratch (__device__ globals; no cudaMalloc allowed)
__device__ float g_K[(size_t)BB * LL * PPQ];   // 16 MB
__device__ float g_Q[(size_t)BB * TTQ * PPQ];  //  4 MB
__device__ float g_S[(size_t)BB * TTQ * LL];   // 64 MB

// ---------------------------------------------------------------------------
// helpers
// ---------------------------------------------------------------------------
__device__ __forceinline__ void mma_fp16(float* d, const uint32_t* a, const uint32_t* b) {
    asm volatile(
        "mma.sync.aligned.m16n8k16.row.col.f32.f16.f16.f32 "
        "{%0,%1,%2,%3}, {%4,%5,%6,%7}, {%8,%9}, {%0,%1,%2,%3};"
        : "+f"(d[0]), "+f"(d[1]), "+f"(d[2]), "+f"(d[3])
        : "r"(a[0]), "r"(a[1]), "r"(a[2]), "r"(a[3]), "r"(b[0]), "r"(b[1]));
}

__device__ __forceinline__ uint32_t h2_u32(__half2 h) {
    return *reinterpret_cast<uint32_t*>(&h);
}

// Split float pair -> (hi half2, lo half2). fp16 products are exact in fp32.
__device__ __forceinline__ void split2(float x, float y, uint32_t& hi, uint32_t& lo) {
    __half2 h = __floats2half2_rn(x, y);
    float2 hb = __half22float2(h);
    __half2 l = __floats2half2_rn(x - hb.x, y - hb.y);
    hi = h2_u32(h);
    lo = h2_u32(l);
}

// ---------------------------------------------------------------------------
// fp16 split tensor-core GEMM: C[M,N] = scale * A[M,K] * op(B)
//   BT=true : B is [N,K] row-major (NT);  BT=false: B is [K,N] row-major (NN)
//   TERMS=3: aH*bH + aH*bL + aL*bH  (rel err ~2^-22 class)
//   TERMS=2: aH*(bH + bL)           (A effectively fp16)
//   TERMS=1: aH*bH                  (both fp16; err ~2^-12 RMS)
// Block tile 128x128, BK=32, 256 threads (8 warps, 64x32 warp tiles).
// SMEM stages hold PRE-SPLIT half data:
//   A_hi [128][40] halves @0, A_lo @5120
//   NT B: B_hi [128][40] @10240, B_lo @15360
//   NN B: B_hi [32][136] @10240, B_lo @14592
// Stage = 20480 halves = 40960 B; 2 stages.
// Optional per-column int32 mask (logits): nonzero -> -FLT_MAX.
// ---------------------------------------------------------------------------
#define STAGE_H 20480
#define SMEM_GEMM (2 * STAGE_H * 2)   // 81920 bytes

template <bool BT, int TERMS>
__global__ __launch_bounds__(256)
void fp16x3_gemm(const float* __restrict__ A, const float* __restrict__ B,
                 float* __restrict__ C,
                 int K, long lda, long ldb, long ldc,
                 long sA, long sB, long sC,
                 float scale, const int* __restrict__ mask, long maskStride)
{
    extern __shared__ __align__(16) uint16_t smh[];

    const int tid  = threadIdx.x;
    const int wid  = tid >> 5;
    const int lane = tid & 31;
    const int grp  = lane >> 2;       // 0..7
    const int tig  = lane & 3;        // 0..3
    const int wm   = (wid & 1) * 64;  // warp m offset
    const int wn   = (wid >> 1) * 32; // warp n offset

    const int bz = blockIdx.z;
    A += (long)bz * sA;
    B += (long)bz * sB;
    C += (long)bz * sC;
    if (mask) mask += (long)bz * maskStride;

    const long row0 = (long)blockIdx.y * 128;
    const long col0 = (long)blockIdx.x * 128;

    const int nIter = K >> 5;   // BK = 32

    float4 rA[4], rB[4];

    auto load_tile = [&](int it) {
        const float* pA = A + row0 * lda + (long)it * 32;
#pragma unroll
        for (int p = 0; p < 4; ++p) {
            const int f = p * 256 + tid;
            rA[p] = *reinterpret_cast<const float4*>(pA + (long)(f >> 3) * lda + (f & 7) * 4);
        }
        if (BT) {
            const float* pB = B + col0 * ldb + (long)it * 32;
#pragma unroll
            for (int p = 0; p < 4; ++p) {
                const int f = p * 256 + tid;
                rB[p] = *reinterpret_cast<const float4*>(pB + (long)(f >> 3) * ldb + (f & 7) * 4);
            }
        } else {
            const float* pB = B + (long)it * 32 * ldb + col0;
#pragma unroll
            for (int p = 0; p < 4; ++p) {
                const int f = p * 256 + tid;
                rB[p] = *reinterpret_cast<const float4*>(pB + (long)(f >> 5) * ldb + (f & 31) * 4);
            }
        }
    };

    auto store_tile = [&](uint16_t* st) {
#pragma unroll
        for (int p = 0; p < 4; ++p) {
            const int f = p * 256 + tid;
            {   // A: [m][40] halves, hi @0, lo @5120
                const int m = f >> 3, kc = (f & 7) * 4;
                float4 v = rA[p];
                uint32_t h0, l0, h1, l1;
                split2(v.x, v.y, h0, l0);
                split2(v.z, v.w, h1, l1);
                *reinterpret_cast<uint2*>(st + m * 40 + kc) = make_uint2(h0, h1);
                if (TERMS == 3)
                    *reinterpret_cast<uint2*>(st + 5120 + m * 40 + kc) = make_uint2(l0, l1);
            }
            if (BT) {   // B: [n][40] halves, hi @10240, lo @15360
                const int n = f >> 3, kc = (f & 7) * 4;
                float4 v = rB[p];
                uint32_t h0, l0, h1, l1;
                split2(v.x, v.y, h0, l0);
                split2(v.z, v.w, h1, l1);
                *reinterpret_cast<uint2*>(st + 10240 + n * 40 + kc) = make_uint2(h0, h1);
                if (TERMS >= 2)
                    *reinterpret_cast<uint2*>(st + 15360 + n * 40 + kc) = make_uint2(l0, l1);
            } else {    // B: [k][136] halves, hi @10240, lo @14592
                const int k = f >> 5, nc = (f & 31) * 4;
                float4 v = rB[p];
                uint32_t h0, l0, h1, l1;
                split2(v.x, v.y, h0, l0);
                split2(v.z, v.w, h1, l1);
                *reinterpret_cast<uint2*>(st + 10240 + k * 136 + nc) = make_uint2(h0, h1);
                if (TERMS >= 2)
                    *reinterpret_cast<uint2*>(st + 14592 + k * 136 + nc) = make_uint2(l0, l1);
            }
        }
    };

    float acc[4][4][4];
#pragma unroll
    for (int i = 0; i < 4; ++i)
#pragma unroll
        for (int j = 0; j < 4; ++j)
#pragma unroll
            for (int r = 0; r < 4; ++r) acc[i][j][r] = 0.0f;

    load_tile(0);
    store_tile(smh);
    __syncthreads();

    for (int it = 0; it < nIter; ++it) {
        const bool more = (it + 1 < nIter);
        if (more) load_tile(it + 1);

        const uint16_t* st = smh + (it & 1) * STAGE_H;
        const uint32_t* sw = reinterpret_cast<const uint32_t*>(st);

#pragma unroll
        for (int ks = 0; ks < 2; ++ks) {
            uint32_t aH[4][4], aL[4][4], bH[4][2], bL[4][2];
#pragma unroll
            for (int i = 0; i < 4; ++i) {
                const int r  = wm + i * 16 + grp;
                const int w0 = r * 20 + tig + 8 * ks;
                const int w1 = (r + 8) * 20 + tig + 8 * ks;
                aH[i][0] = sw[w0];     aH[i][1] = sw[w1];
                aH[i][2] = sw[w0 + 4]; aH[i][3] = sw[w1 + 4];
                if (TERMS == 3) {
                    aL[i][0] = sw[2560 + w0];     aL[i][1] = sw[2560 + w1];
                    aL[i][2] = sw[2560 + w0 + 4]; aL[i][3] = sw[2560 + w1 + 4];
                }
            }
#pragma unroll
            for (int j = 0; j < 4; ++j) {
                const int n = wn + j * 8 + grp;
                if (BT) {
                    const int w0 = 5120 + n * 20 + tig + 8 * ks;
                    bH[j][0] = sw[w0];        bH[j][1] = sw[w0 + 4];
                    if (TERMS >= 2) {
                        bL[j][0] = sw[2560 + w0]; bL[j][1] = sw[2560 + w0 + 4];
                    }
                } else {
                    const int kb = 2 * tig + 16 * ks;
                    const uint16_t* bh = st + 10240;
                    const uint16_t* bl = st + 14592;
                    bH[j][0] = (uint32_t)bh[kb * 136 + n]       | ((uint32_t)bh[(kb + 1) * 136 + n] << 16);
                    bH[j][1] = (uint32_t)bh[(kb + 8) * 136 + n] | ((uint32_t)bh[(kb + 9) * 136 + n] << 16);
                    if (TERMS >= 2) {
                        bL[j][0] = (uint32_t)bl[kb * 136 + n]       | ((uint32_t)bl[(kb + 1) * 136 + n] << 16);
                        bL[j][1] = (uint32_t)bl[(kb + 8) * 136 + n] | ((uint32_t)bl[(kb + 9) * 136 + n] << 16);
                    }
                }
            }
            // Separate sweeps: dependent MMAs on one accumulator are 16 apart.
#pragma unroll
            for (int i = 0; i < 4; ++i)
#pragma unroll
                for (int j = 0; j < 4; ++j)
                    mma_fp16(acc[i][j], aH[i], bH[j]);
            if (TERMS >= 2) {
#pragma unroll
                for (int i = 0; i < 4; ++i)
#pragma unroll
                    for (int j = 0; j < 4; ++j)
                        mma_fp16(acc[i][j], aH[i], bL[j]);
            }
            if (TERMS == 3) {
#pragma unroll
                for (int i = 0; i < 4; ++i)
#pragma unroll
                    for (int j = 0; j < 4; ++j)
                        mma_fp16(acc[i][j], aL[i], bH[j]);
            }
        }

        if (more) store_tile(smh + ((it + 1) & 1) * STAGE_H);
        __syncthreads();
    }

    // Epilogue: register -> gmem (float2 per row-pair), scale + mask
#pragma unroll
    for (int i = 0; i < 4; ++i) {
        const long r0 = row0 + wm + i * 16 + grp;
#pragma unroll
        for (int j = 0; j < 4; ++j) {
            const long gc = col0 + wn + j * 8 + tig * 2;
            float x0 = acc[i][j][0] * scale, x1 = acc[i][j][1] * scale;
            float y0 = acc[i][j][2] * scale, y1 = acc[i][j][3] * scale;
            if (mask) {
                const bool m0 = mask[gc] != 0, m1 = mask[gc + 1] != 0;
                if (m0) { x0 = -FLT_MAX; y0 = -FLT_MAX; }
                if (m1) { x1 = -FLT_MAX; y1 = -FLT_MAX; }
            }
            *reinterpret_cast<float2*>(C + r0 * ldc + gc)       = make_float2(x0, x1);
            *reinterpret_cast<float2*>(C + (r0 + 8) * ldc + gc) = make_float2(y0, y1);
        }
    }
}

// ---------------------------------------------------------------------------
// Row softmax over LL (float4 I/O). Also serves as the in-run clock probe:
// at healthy clocks this kernel reads ~25 us / ~2.9 TB/s.
// ---------------------------------------------------------------------------
__global__ __launch_bounds__(256)
void softmax_kernel(float* __restrict__ S)
{
    __shared__ float4 buf[LL / 4];
    __shared__ float red[256];

    const int tid = threadIdx.x;
    float4* p = reinterpret_cast<float4*>(S + (long)blockIdx.x * LL);

    float m = -FLT_MAX;
#pragma unroll
    for (int i = tid; i < LL / 4; i += 256) {
        float4 v = p[i];
        buf[i] = v;
        m = fmaxf(m, fmaxf(fmaxf(v.x, v.y), fmaxf(v.z, v.w)));
    }
    red[tid] = m;
    __syncthreads();
    for (int s = 128; s > 0; s >>= 1) {
        if (tid < s) red[tid] = fmaxf(red[tid], red[tid + s]);
        __syncthreads();
    }
    m = red[0];
    __syncthreads();

    float sum = 0.0f;
#pragma unroll
    for (int i = tid; i < LL / 4; i += 256) {
        float4 v = buf[i];
        v.x = __expf(v.x - m); v.y = __expf(v.y - m);
        v.z = __expf(v.z - m); v.w = __expf(v.w - m);
        buf[i] = v;
        sum += v.x + v.y + v.z + v.w;
    }
    red[tid] = sum;
    __syncthreads();
    for (int s = 128; s > 0; s >>= 1) {
        if (tid < s) red[tid] += red[tid + s];
        __syncthreads();
    }
    const float inv = 1.0f / red[0];

#pragma unroll
    for (int i = tid; i < LL / 4; i += 256) {
        float4 v = buf[i];
        v.x *= inv; v.y *= inv; v.z *= inv; v.w *= inv;
        p[i] = v;
    }
}

// ---------------------------------------------------------------------------
// Launch. Inputs: H [B,L,DH] f32, G [B,T,DG] f32, mask [B,L] int32,
// Wk_w [P,DH] f32, Wq_w [P,DG] f32. Output Z [B,T,DH] f32.
// ---------------------------------------------------------------------------
extern "C" void kernel_launch(void* const* d_in, const int* in_sizes, int n_in,
                              void* d_out, int out_size)
{
    const float* H    = (const float*)d_in[0];
    const float* G    = (const float*)d_in[1];
    const int*   mask = (const int*)d_in[2];
    const float* Wk   = (const float*)d_in[3];
    const float* Wq   = (const float*)d_in[4];
    float*       Z    = (float*)d_out;

    float *gK, *gQ, *gS;
    cudaGetSymbolAddress((void**)&gK, g_K);
    cudaGetSymbolAddress((void**)&gQ, g_Q);
    cudaGetSymbolAddress((void**)&gS, g_S);

    cudaFuncSetAttribute(fp16x3_gemm<true, 3>,
                         cudaFuncAttributeMaxDynamicSharedMemorySize, SMEM_GEMM);
    cudaFuncSetAttribute(fp16x3_gemm<false, 1>,
                         cudaFuncAttributeMaxDynamicSharedMemorySize, SMEM_GEMM);

    // 1) K = H * Wk^T : [B*L, DH] x [P, DH]^T -> [B*L, P]
    fp16x3_gemm<true, 3><<<dim3(PPQ / 128, (BB * LL) / 128, 1), 256, SMEM_GEMM>>>(
        H, Wk, gK, DHQ, DHQ, DHQ, PPQ, 0, 0, 0, 1.0f, nullptr, 0);

    // 2) Q = G * Wq^T : [B*T, DG] x [P, DG]^T -> [B*T, P]
    fp16x3_gemm<true, 3><<<dim3(PPQ / 128, (BB * TTQ) / 128, 1), 256, SMEM_GEMM>>>(
        G, Wq, gQ, DGQ, DGQ, DGQ, PPQ, 0, 0, 0, 1.0f, nullptr, 0);

    // 3) S = scale * Q * K^T (masked) : per batch [T, P] x [L, P]^T -> [T, L]
    fp16x3_gemm<true, 3><<<dim3(LL / 128, TTQ / 128, BB), 256, SMEM_GEMM>>>(
        gQ, gK, gS, PPQ, PPQ, PPQ, LL,
        (long)TTQ * PPQ, (long)LL * PPQ, (long)TTQ * LL,
        0.0625f, mask, (long)LL);

    // 4) softmax over L
    softmax_kernel<<<BB * TTQ, 256>>>(gS);

    // 5) Z = alpha * H : per batch [T, L] x [L, DH] (NN) -> [T, DH]
    //    1-term: alpha_hi * H_hi — error ~2^-12 RMS, norm-relative (weighted
    //    average: signal and noise both scale with sqrt(sum alpha^2)).
    fp16x3_gemm<false, 1><<<dim3(DHQ / 128, TTQ / 128, BB), 256, SMEM_GEMM>>>(
        gS, H, Z, LL, LL, DHQ, DHQ,
        (long)TTQ * LL, (long)LL * DHQ, (long)TTQ * DHQ,
        1.0f, nullptr, 0);
}

// round 12
// speedup vs baseline: 1.9336x; 1.3240x over previous
#include <cuda_runtime.h>
#include <cuda_fp16.h>
#include <cstdint>
#include <float.h>

// Problem constants
#define BB 4
#define LL 4096
#define DHQ 1024
#define TTQ 1024
#define DGQ 768
#define PPQ 256

// Scratch (__device__ globals; no cudaMalloc allowed)
__device__ float  g_K [(size_t)BB * LL  * PPQ];  // 16 MB
__device__ float  g_Q [(size_t)BB * TTQ * PPQ];  //  4 MB
__device__ float  g_S [(size_t)BB * TTQ * LL ];  // 64 MB logits
__device__ __half g_Ah[(size_t)BB * TTQ * LL ];  // 32 MB alpha (fp16)
__device__ __half g_Hh[(size_t)BB * LL  * DHQ];  // 32 MB H (fp16)

// ---------------------------------------------------------------------------
// helpers
// ---------------------------------------------------------------------------
__device__ __forceinline__ void mma_fp16(float* d, const uint32_t* a, const uint32_t* b) {
    asm volatile(
        "mma.sync.aligned.m16n8k16.row.col.f32.f16.f16.f32 "
        "{%0,%1,%2,%3}, {%4,%5,%6,%7}, {%8,%9}, {%0,%1,%2,%3};"
        : "+f"(d[0]), "+f"(d[1]), "+f"(d[2]), "+f"(d[3])
        : "r"(a[0]), "r"(a[1]), "r"(a[2]), "r"(a[3]), "r"(b[0]), "r"(b[1]));
}

__device__ __forceinline__ uint32_t h2_u32(__half2 h) {
    return *reinterpret_cast<uint32_t*>(&h);
}

__device__ __forceinline__ void split2(float x, float y, uint32_t& hi, uint32_t& lo) {
    __half2 h = __floats2half2_rn(x, y);
    float2 hb = __half22float2(h);
    __half2 l = __floats2half2_rn(x - hb.x, y - hb.y);
    hi = h2_u32(h);
    lo = h2_u32(l);
}

__device__ __forceinline__ void cp16(void* sdst, const void* gsrc) {
    uint32_t a = (uint32_t)__cvta_generic_to_shared(sdst);
    asm volatile("cp.async.cg.shared.global [%0], [%1], 16;" :: "r"(a), "l"(gsrc));
}
#define CP_COMMIT() asm volatile("cp.async.commit_group;" ::: "memory")
#define CP_WAIT1()  asm volatile("cp.async.wait_group 1;" ::: "memory")

__device__ __forceinline__ void ldsm_x4(uint32_t* r, uint32_t saddr) {
    asm volatile("ldmatrix.sync.aligned.m8n8.x4.shared.b16 {%0,%1,%2,%3}, [%4];"
                 : "=r"(r[0]), "=r"(r[1]), "=r"(r[2]), "=r"(r[3]) : "r"(saddr));
}
__device__ __forceinline__ void ldsm_x4_t(uint32_t* r, uint32_t saddr) {
    asm volatile("ldmatrix.sync.aligned.m8n8.x4.trans.shared.b16 {%0,%1,%2,%3}, [%4];"
                 : "=r"(r[0]), "=r"(r[1]), "=r"(r[2]), "=r"(r[3]) : "r"(saddr));
}

// ---------------------------------------------------------------------------
// fp16x3 NT GEMM (3-term split) — used for K-proj, Q-proj, logits.
// C[M,N] = scale * A[M,K] * B[N,K]^T, optional int32 column mask.
// (unchanged from the 494us baseline)
// ---------------------------------------------------------------------------
#define STAGE_H 20480
#define SMEM_GEMM (2 * STAGE_H * 2)   // 81920 bytes

__global__ __launch_bounds__(256)
void fp16x3_gemm_nt(const float* __restrict__ A, const float* __restrict__ B,
                    float* __restrict__ C,
                    int K, long lda, long ldb, long ldc,
                    long sA, long sB, long sC,
                    float scale, const int* __restrict__ mask, long maskStride)
{
    extern __shared__ __align__(16) uint16_t smh[];

    const int tid  = threadIdx.x;
    const int wid  = tid >> 5;
    const int lane = tid & 31;
    const int grp  = lane >> 2;
    const int tig  = lane & 3;
    const int wm   = (wid & 1) * 64;
    const int wn   = (wid >> 1) * 32;

    const int bz = blockIdx.z;
    A += (long)bz * sA;
    B += (long)bz * sB;
    C += (long)bz * sC;
    if (mask) mask += (long)bz * maskStride;

    const long row0 = (long)blockIdx.y * 128;
    const long col0 = (long)blockIdx.x * 128;
    const int nIter = K >> 5;

    float4 rA[4], rB[4];

    auto load_tile = [&](int it) {
        const float* pA = A + row0 * lda + (long)it * 32;
#pragma unroll
        for (int p = 0; p < 4; ++p) {
            const int f = p * 256 + tid;
            rA[p] = *reinterpret_cast<const float4*>(pA + (long)(f >> 3) * lda + (f & 7) * 4);
        }
        const float* pB = B + col0 * ldb + (long)it * 32;
#pragma unroll
        for (int p = 0; p < 4; ++p) {
            const int f = p * 256 + tid;
            rB[p] = *reinterpret_cast<const float4*>(pB + (long)(f >> 3) * ldb + (f & 7) * 4);
        }
    };

    auto store_tile = [&](uint16_t* st) {
#pragma unroll
        for (int p = 0; p < 4; ++p) {
            const int f = p * 256 + tid;
            {
                const int m = f >> 3, kc = (f & 7) * 4;
                float4 v = rA[p];
                uint32_t h0, l0, h1, l1;
                split2(v.x, v.y, h0, l0);
                split2(v.z, v.w, h1, l1);
                *reinterpret_cast<uint2*>(st + m * 40 + kc)        = make_uint2(h0, h1);
                *reinterpret_cast<uint2*>(st + 5120 + m * 40 + kc) = make_uint2(l0, l1);
            }
            {
                const int n = f >> 3, kc = (f & 7) * 4;
                float4 v = rB[p];
                uint32_t h0, l0, h1, l1;
                split2(v.x, v.y, h0, l0);
                split2(v.z, v.w, h1, l1);
                *reinterpret_cast<uint2*>(st + 10240 + n * 40 + kc) = make_uint2(h0, h1);
                *reinterpret_cast<uint2*>(st + 15360 + n * 40 + kc) = make_uint2(l0, l1);
            }
        }
    };

    float acc[4][4][4];
#pragma unroll
    for (int i = 0; i < 4; ++i)
#pragma unroll
        for (int j = 0; j < 4; ++j)
#pragma unroll
            for (int r = 0; r < 4; ++r) acc[i][j][r] = 0.0f;

    load_tile(0);
    store_tile(smh);
    __syncthreads();

    for (int it = 0; it < nIter; ++it) {
        const bool more = (it + 1 < nIter);
        if (more) load_tile(it + 1);

        const uint32_t* sw = reinterpret_cast<const uint32_t*>(smh + (it & 1) * STAGE_H);

#pragma unroll
        for (int ks = 0; ks < 2; ++ks) {
            uint32_t aH[4][4], aL[4][4], bH[4][2], bL[4][2];
#pragma unroll
            for (int i = 0; i < 4; ++i) {
                const int r  = wm + i * 16 + grp;
                const int w0 = r * 20 + tig + 8 * ks;
                const int w1 = (r + 8) * 20 + tig + 8 * ks;
                aH[i][0] = sw[w0];            aH[i][1] = sw[w1];
                aH[i][2] = sw[w0 + 4];        aH[i][3] = sw[w1 + 4];
                aL[i][0] = sw[2560 + w0];     aL[i][1] = sw[2560 + w1];
                aL[i][2] = sw[2560 + w0 + 4]; aL[i][3] = sw[2560 + w1 + 4];
            }
#pragma unroll
            for (int j = 0; j < 4; ++j) {
                const int n  = wn + j * 8 + grp;
                const int w0 = 5120 + n * 20 + tig + 8 * ks;
                bH[j][0] = sw[w0];        bH[j][1] = sw[w0 + 4];
                bL[j][0] = sw[2560 + w0]; bL[j][1] = sw[2560 + w0 + 4];
            }
#pragma unroll
            for (int i = 0; i < 4; ++i)
#pragma unroll
                for (int j = 0; j < 4; ++j)
                    mma_fp16(acc[i][j], aH[i], bH[j]);
#pragma unroll
            for (int i = 0; i < 4; ++i)
#pragma unroll
                for (int j = 0; j < 4; ++j)
                    mma_fp16(acc[i][j], aH[i], bL[j]);
#pragma unroll
            for (int i = 0; i < 4; ++i)
#pragma unroll
                for (int j = 0; j < 4; ++j)
                    mma_fp16(acc[i][j], aL[i], bH[j]);
        }

        if (more) store_tile(smh + ((it + 1) & 1) * STAGE_H);
        __syncthreads();
    }

#pragma unroll
    for (int i = 0; i < 4; ++i) {
        const long r0 = row0 + wm + i * 16 + grp;
#pragma unroll
        for (int j = 0; j < 4; ++j) {
            const long gc = col0 + wn + j * 8 + tig * 2;
            float x0 = acc[i][j][0] * scale, x1 = acc[i][j][1] * scale;
            float y0 = acc[i][j][2] * scale, y1 = acc[i][j][3] * scale;
            if (mask) {
                const bool m0 = mask[gc] != 0, m1 = mask[gc + 1] != 0;
                if (m0) { x0 = -FLT_MAX; y0 = -FLT_MAX; }
                if (m1) { x1 = -FLT_MAX; y1 = -FLT_MAX; }
            }
            *reinterpret_cast<float2*>(C + r0 * ldc + gc)       = make_float2(x0, x1);
            *reinterpret_cast<float2*>(C + (r0 + 8) * ldc + gc) = make_float2(y0, y1);
        }
    }
}

// ---------------------------------------------------------------------------
// Pure fp16 NN GEMM (Z = alpha * H), ldmatrix fragments, cp.async 3-stage.
// A: [M,K] half row-major (alpha), B: [K,N] half row-major (H), C fp32.
// Tile 128x128, BK=32, 256 threads, warp tile 64x32.
// SMEM stage: A [128][40] halves @0 (5120), B [32][136] halves @5120 (4352).
// ---------------------------------------------------------------------------
#define ZSTAGE_H 9472
#define ZNSTAGE 3
#define SMEM_Z (ZNSTAGE * ZSTAGE_H * 2)   // 56832 bytes

__global__ __launch_bounds__(256)
void fp16_gemm_nn(const __half* __restrict__ A, const __half* __restrict__ B,
                  float* __restrict__ C,
                  int K, long lda, long ldb, long ldc,
                  long sA, long sB, long sC)
{
    extern __shared__ __align__(16) __half smz[];

    const int tid  = threadIdx.x;
    const int wid  = tid >> 5;
    const int lane = tid & 31;
    const int grp  = lane >> 2;
    const int tig  = lane & 3;
    const int wm   = (wid & 1) * 64;
    const int wn   = (wid >> 1) * 32;

    const int bz = blockIdx.z;
    A += (long)bz * sA;
    B += (long)bz * sB;
    C += (long)bz * sC;

    const long row0 = (long)blockIdx.y * 128;
    const long col0 = (long)blockIdx.x * 128;
    const int nIter = K >> 5;

    // ldmatrix per-lane element offsets (halves, within a stage):
    //  A: row = wm + (lane&15), col = 8*(lane>>4); matrices = (m0-7,k0-7),
    //     (m8-15,k0-7), (m0-7,k8-15), (m8-15,k8-15) -> exact A-frag order.
    const uint32_t aoff = (uint32_t)((wm + (lane & 15)) * 40 + 8 * (lane >> 4));
    //  B (trans): row(k) = lane&15, col = wn + 8*(lane>>4) + 16*jp; matrices =
    //     (k0-7,nj), (k8-15,nj), (k0-7,nj+8), (k8-15,nj+8) -> {b0,b1} x 2 j.
    const uint32_t boff = (uint32_t)(5120 + (lane & 15) * 136 + wn + 8 * (lane >> 4));

    const uint32_t smz_base = (uint32_t)__cvta_generic_to_shared(smz);

    auto issue_stage = [&](int it) {
        __half* sa = smz + (it % ZNSTAGE) * ZSTAGE_H;
        __half* sb = sa + 5120;
        const __half* pA = A + row0 * lda + (long)it * 32;
#pragma unroll
        for (int p = 0; p < 2; ++p) {
            const int f = p * 256 + tid;         // 512 chunks: m = f>>2, kc=(f&3)*8
            const int m = f >> 2, kc = (f & 3) * 8;
            cp16(sa + m * 40 + kc, pA + (long)m * lda + kc);
        }
        const __half* pB = B + (long)it * 32 * ldb + col0;
#pragma unroll
        for (int p = 0; p < 2; ++p) {
            const int f = p * 256 + tid;         // 512 chunks: k = f>>4, nc=(f&15)*8
            const int k = f >> 4, nc = (f & 15) * 8;
            cp16(sb + k * 136 + nc, pB + (long)k * ldb + nc);
        }
    };

    float acc[4][4][4];
#pragma unroll
    for (int i = 0; i < 4; ++i)
#pragma unroll
        for (int j = 0; j < 4; ++j)
#pragma unroll
            for (int r = 0; r < 4; ++r) acc[i][j][r] = 0.0f;

    issue_stage(0); CP_COMMIT();
    issue_stage(1); CP_COMMIT();

    for (int it = 0; it < nIter; ++it) {
        CP_WAIT1();
        __syncthreads();

        if (it + 2 < nIter) issue_stage(it + 2);
        CP_COMMIT();

        const uint32_t stb = smz_base + (uint32_t)((it % ZNSTAGE) * ZSTAGE_H) * 2;

#pragma unroll
        for (int s = 0; s < 2; ++s) {
            uint32_t aF[4][4], bF[2][4];
#pragma unroll
            for (int i = 0; i < 4; ++i)
                ldsm_x4(aF[i], stb + (aoff + i * 16 * 40 + s * 16) * 2);
#pragma unroll
            for (int jp = 0; jp < 2; ++jp)
                ldsm_x4_t(bF[jp], stb + (boff + s * 16 * 136 + jp * 16) * 2);
#pragma unroll
            for (int i = 0; i < 4; ++i) {
#pragma unroll
                for (int jp = 0; jp < 2; ++jp) {
                    mma_fp16(acc[i][2 * jp + 0], aF[i], &bF[jp][0]);
                    mma_fp16(acc[i][2 * jp + 1], aF[i], &bF[jp][2]);
                }
            }
        }
        __syncthreads();
    }

#pragma unroll
    for (int i = 0; i < 4; ++i) {
        const long r0 = row0 + wm + i * 16 + grp;
#pragma unroll
        for (int j = 0; j < 4; ++j) {
            const long gc = col0 + wn + j * 8 + tig * 2;
            *reinterpret_cast<float2*>(C + r0 * ldc + gc) =
                make_float2(acc[i][j][0], acc[i][j][1]);
            *reinterpret_cast<float2*>(C + (r0 + 8) * ldc + gc) =
                make_float2(acc[i][j][2], acc[i][j][3]);
        }
    }
}

// ---------------------------------------------------------------------------
// H -> fp16 conversion (one-shot, ~96 MB traffic)
// ---------------------------------------------------------------------------
__global__ __launch_bounds__(256)
void h2half_kernel(const float* __restrict__ X, __half* __restrict__ Y, long n4)
{
    const long i = (long)blockIdx.x * 256 + threadIdx.x;
    if (i < n4) {
        float4 v = reinterpret_cast<const float4*>(X)[i];
        uint2 o;
        o.x = h2_u32(__floats2half2_rn(v.x, v.y));
        o.y = h2_u32(__floats2half2_rn(v.z, v.w));
        reinterpret_cast<uint2*>(Y)[i] = o;
    }
}

// ---------------------------------------------------------------------------
// Row softmax over LL; reads fp32 logits, writes fp16 alpha.
// Clock probe: healthy runs show ~20 us here.
// ---------------------------------------------------------------------------
__global__ __launch_bounds__(256)
void softmax_kernel(const float* __restrict__ S, __half* __restrict__ Ah)
{
    __shared__ float4 buf[LL / 4];
    __shared__ float red[256];

    const int tid = threadIdx.x;
    const float4* p = reinterpret_cast<const float4*>(S + (long)blockIdx.x * LL);
    uint2* out = reinterpret_cast<uint2*>(Ah + (long)blockIdx.x * LL);

    float m = -FLT_MAX;
#pragma unroll
    for (int i = tid; i < LL / 4; i += 256) {
        float4 v = p[i];
        buf[i] = v;
        m = fmaxf(m, fmaxf(fmaxf(v.x, v.y), fmaxf(v.z, v.w)));
    }
    red[tid] = m;
    __syncthreads();
    for (int s = 128; s > 0; s >>= 1) {
        if (tid < s) red[tid] = fmaxf(red[tid], red[tid + s]);
        __syncthreads();
    }
    m = red[0];
    __syncthreads();

    float sum = 0.0f;
#pragma unroll
    for (int i = tid; i < LL / 4; i += 256) {
        float4 v = buf[i];
        v.x = __expf(v.x - m); v.y = __expf(v.y - m);
        v.z = __expf(v.z - m); v.w = __expf(v.w - m);
        buf[i] = v;
        sum += v.x + v.y + v.z + v.w;
    }
    red[tid] = sum;
    __syncthreads();
    for (int s = 128; s > 0; s >>= 1) {
        if (tid < s) red[tid] += red[tid + s];
        __syncthreads();
    }
    const float inv = 1.0f / red[0];

#pragma unroll
    for (int i = tid; i < LL / 4; i += 256) {
        float4 v = buf[i];
        uint2 o;
        o.x = h2_u32(__floats2half2_rn(v.x * inv, v.y * inv));
        o.y = h2_u32(__floats2half2_rn(v.z * inv, v.w * inv));
        out[i] = o;
    }
}

// ---------------------------------------------------------------------------
// Launch. Inputs: H [B,L,DH] f32, G [B,T,DG] f32, mask [B,L] int32,
// Wk_w [P,DH] f32, Wq_w [P,DG] f32. Output Z [B,T,DH] f32.
// ---------------------------------------------------------------------------
extern "C" void kernel_launch(void* const* d_in, const int* in_sizes, int n_in,
                              void* d_out, int out_size)
{
    const float* H    = (const float*)d_in[0];
    const float* G    = (const float*)d_in[1];
    const int*   mask = (const int*)d_in[2];
    const float* Wk   = (const float*)d_in[3];
    const float* Wq   = (const float*)d_in[4];
    float*       Z    = (float*)d_out;

    float  *gK, *gQ, *gS;
    __half *gAh, *gHh;
    cudaGetSymbolAddress((void**)&gK,  g_K);
    cudaGetSymbolAddress((void**)&gQ,  g_Q);
    cudaGetSymbolAddress((void**)&gS,  g_S);
    cudaGetSymbolAddress((void**)&gAh, g_Ah);
    cudaGetSymbolAddress((void**)&gHh, g_Hh);

    cudaFuncSetAttribute(fp16x3_gemm_nt,
                         cudaFuncAttributeMaxDynamicSharedMemorySize, SMEM_GEMM);
    cudaFuncSetAttribute(fp16_gemm_nn,
                         cudaFuncAttributeMaxDynamicSharedMemorySize, SMEM_Z);

    // 0) H -> fp16 (for the Z GEMM B-operand)
    {
        const long n4 = (long)BB * LL * DHQ / 4;
        h2half_kernel<<<(unsigned)((n4 + 255) / 256), 256>>>(H, gHh, n4);
    }

    // 1) K = H * Wk^T : [B*L, DH] x [P, DH]^T -> [B*L, P]
    fp16x3_gemm_nt<<<dim3(PPQ / 128, (BB * LL) / 128, 1), 256, SMEM_GEMM>>>(
        H, Wk, gK, DHQ, DHQ, DHQ, PPQ, 0, 0, 0, 1.0f, nullptr, 0);

    // 2) Q = G * Wq^T : [B*T, DG] x [P, DG]^T -> [B*T, P]
    fp16x3_gemm_nt<<<dim3(PPQ / 128, (BB * TTQ) / 128, 1), 256, SMEM_GEMM>>>(
        G, Wq, gQ, DGQ, DGQ, DGQ, PPQ, 0, 0, 0, 1.0f, nullptr, 0);

    // 3) S = scale * Q * K^T (masked) : per batch [T, P] x [L, P]^T -> [T, L]
    fp16x3_gemm_nt<<<dim3(LL / 128, TTQ / 128, BB), 256, SMEM_GEMM>>>(
        gQ, gK, gS, PPQ, PPQ, PPQ, LL,
        (long)TTQ * PPQ, (long)LL * PPQ, (long)TTQ * LL,
        0.0625f, mask, (long)LL);

    // 4) softmax over L, emitting fp16 alpha
    softmax_kernel<<<BB * TTQ, 256>>>(gS, gAh);

    // 5) Z = alpha_h * H_h : per batch [T, L] x [L, DH] -> [T, DH] (pure fp16)
    fp16_gemm_nn<<<dim3(DHQ / 128, TTQ / 128, BB), 256, SMEM_Z>>>(
        gAh, gHh, Z, LL, LL, DHQ, DHQ,
        (long)TTQ * LL, (long)LL * DHQ, (long)TTQ * DHQ);
}

// round 15
// speedup vs baseline: 2.1427x; 1.1081x over previous
#include <cuda_runtime.h>
#include <cuda_fp16.h>
#include <cstdint>
#include <float.h>

// Problem constants
#define BB 4
#define LL 4096
#define DHQ 1024
#define TTQ 1024
#define DGQ 768
#define PPQ 256

// Scratch (__device__ globals; no cudaMalloc allowed)
__device__ float  g_K [(size_t)BB * LL  * PPQ];  // 16 MB
__device__ float  g_Q [(size_t)BB * TTQ * PPQ];  //  4 MB
__device__ float  g_S [(size_t)BB * TTQ * LL ];  // 64 MB logits
__device__ __half g_Ah[(size_t)BB * TTQ * LL ];  // 32 MB alpha (fp16)
__device__ __half g_Hh[(size_t)BB * LL  * DHQ];  // 32 MB H (fp16)

// ---------------------------------------------------------------------------
// helpers
// ---------------------------------------------------------------------------
__device__ __forceinline__ void mma_fp16(float* d, const uint32_t* a, const uint32_t* b) {
    asm volatile(
        "mma.sync.aligned.m16n8k16.row.col.f32.f16.f16.f32 "
        "{%0,%1,%2,%3}, {%4,%5,%6,%7}, {%8,%9}, {%0,%1,%2,%3};"
        : "+f"(d[0]), "+f"(d[1]), "+f"(d[2]), "+f"(d[3])
        : "r"(a[0]), "r"(a[1]), "r"(a[2]), "r"(a[3]), "r"(b[0]), "r"(b[1]));
}

__device__ __forceinline__ uint32_t h2_u32(__half2 h) {
    return *reinterpret_cast<uint32_t*>(&h);
}

__device__ __forceinline__ void split2(float x, float y, uint32_t& hi, uint32_t& lo) {
    __half2 h = __floats2half2_rn(x, y);
    float2 hb = __half22float2(h);
    __half2 l = __floats2half2_rn(x - hb.x, y - hb.y);
    hi = h2_u32(h);
    lo = h2_u32(l);
}

__device__ __forceinline__ void cp16(void* sdst, const void* gsrc) {
    uint32_t a = (uint32_t)__cvta_generic_to_shared(sdst);
    asm volatile("cp.async.cg.shared.global [%0], [%1], 16;" :: "r"(a), "l"(gsrc));
}
#define CP_COMMIT() asm volatile("cp.async.commit_group;" ::: "memory")
#define CP_WAIT1()  asm volatile("cp.async.wait_group 1;" ::: "memory")

__device__ __forceinline__ void ldsm_x4(uint32_t* r, uint32_t saddr) {
    asm volatile("ldmatrix.sync.aligned.m8n8.x4.shared.b16 {%0,%1,%2,%3}, [%4];"
                 : "=r"(r[0]), "=r"(r[1]), "=r"(r[2]), "=r"(r[3]) : "r"(saddr));
}
__device__ __forceinline__ void ldsm_x4_t(uint32_t* r, uint32_t saddr) {
    asm volatile("ldmatrix.sync.aligned.m8n8.x4.trans.shared.b16 {%0,%1,%2,%3}, [%4];"
                 : "=r"(r[0]), "=r"(r[1]), "=r"(r[2]), "=r"(r[3]) : "r"(saddr));
}

// ---------------------------------------------------------------------------
// fp16 split NT GEMM: C[M,N] = scale * A[M,K] * B[N,K]^T
//   TERMS=3: aH*bH + aH*bL + aL*bH   (rel err ~2^-22 class)
//   TERMS=2: aH*bH + aH*bL           (A fp16-quantized, B exact to 22 bits)
// Block tile 128x128, BK=32, 256 threads (8 warps, 64x32 warp tiles).
// SMEM: A_hi [128][40] @0, A_lo @5120 (TERMS=3 only),
//       B_hi [128][40] @10240, B_lo @15360. 2 stages.
// Optional per-column int32 mask (logits): nonzero -> -FLT_MAX.
// ---------------------------------------------------------------------------
#define STAGE_H 20480
#define SMEM_GEMM (2 * STAGE_H * 2)   // 81920 bytes

template <int TERMS>
__global__ __launch_bounds__(256)
void fp16x3_gemm_nt(const float* __restrict__ A, const float* __restrict__ B,
                    float* __restrict__ C,
                    int K, long lda, long ldb, long ldc,
                    long sA, long sB, long sC,
                    float scale, const int* __restrict__ mask, long maskStride)
{
    extern __shared__ __align__(16) uint16_t smh[];

    const int tid  = threadIdx.x;
    const int wid  = tid >> 5;
    const int lane = tid & 31;
    const int grp  = lane >> 2;
    const int tig  = lane & 3;
    const int wm   = (wid & 1) * 64;
    const int wn   = (wid >> 1) * 32;

    const int bz = blockIdx.z;
    A += (long)bz * sA;
    B += (long)bz * sB;
    C += (long)bz * sC;
    if (mask) mask += (long)bz * maskStride;

    const long row0 = (long)blockIdx.y * 128;
    const long col0 = (long)blockIdx.x * 128;
    const int nIter = K >> 5;

    float4 rA[4], rB[4];

    auto load_tile = [&](int it) {
        const float* pA = A + row0 * lda + (long)it * 32;
#pragma unroll
        for (int p = 0; p < 4; ++p) {
            const int f = p * 256 + tid;
            rA[p] = *reinterpret_cast<const float4*>(pA + (long)(f >> 3) * lda + (f & 7) * 4);
        }
        const float* pB = B + col0 * ldb + (long)it * 32;
#pragma unroll
        for (int p = 0; p < 4; ++p) {
            const int f = p * 256 + tid;
            rB[p] = *reinterpret_cast<const float4*>(pB + (long)(f >> 3) * ldb + (f & 7) * 4);
        }
    };

    auto store_tile = [&](uint16_t* st) {
#pragma unroll
        for (int p = 0; p < 4; ++p) {
            const int f = p * 256 + tid;
            {
                const int m = f >> 3, kc = (f & 7) * 4;
                float4 v = rA[p];
                uint32_t h0, l0, h1, l1;
                split2(v.x, v.y, h0, l0);
                split2(v.z, v.w, h1, l1);
                *reinterpret_cast<uint2*>(st + m * 40 + kc) = make_uint2(h0, h1);
                if (TERMS == 3)
                    *reinterpret_cast<uint2*>(st + 5120 + m * 40 + kc) = make_uint2(l0, l1);
            }
            {
                const int n = f >> 3, kc = (f & 7) * 4;
                float4 v = rB[p];
                uint32_t h0, l0, h1, l1;
                split2(v.x, v.y, h0, l0);
                split2(v.z, v.w, h1, l1);
                *reinterpret_cast<uint2*>(st + 10240 + n * 40 + kc) = make_uint2(h0, h1);
                *reinterpret_cast<uint2*>(st + 15360 + n * 40 + kc) = make_uint2(l0, l1);
            }
        }
    };

    float acc[4][4][4];
#pragma unroll
    for (int i = 0; i < 4; ++i)
#pragma unroll
        for (int j = 0; j < 4; ++j)
#pragma unroll
            for (int r = 0; r < 4; ++r) acc[i][j][r] = 0.0f;

    load_tile(0);
    store_tile(smh);
    __syncthreads();

    for (int it = 0; it < nIter; ++it) {
        const bool more = (it + 1 < nIter);
        if (more) load_tile(it + 1);

        const uint32_t* sw = reinterpret_cast<const uint32_t*>(smh + (it & 1) * STAGE_H);

#pragma unroll
        for (int ks = 0; ks < 2; ++ks) {
            uint32_t aH[4][4], aL[4][4], bH[4][2], bL[4][2];
#pragma unroll
            for (int i = 0; i < 4; ++i) {
                const int r  = wm + i * 16 + grp;
                const int w0 = r * 20 + tig + 8 * ks;
                const int w1 = (r + 8) * 20 + tig + 8 * ks;
                aH[i][0] = sw[w0];     aH[i][1] = sw[w1];
                aH[i][2] = sw[w0 + 4]; aH[i][3] = sw[w1 + 4];
                if (TERMS == 3) {
                    aL[i][0] = sw[2560 + w0];     aL[i][1] = sw[2560 + w1];
                    aL[i][2] = sw[2560 + w0 + 4]; aL[i][3] = sw[2560 + w1 + 4];
                }
            }
#pragma unroll
            for (int j = 0; j < 4; ++j) {
                const int n  = wn + j * 8 + grp;
                const int w0 = 5120 + n * 20 + tig + 8 * ks;
                bH[j][0] = sw[w0];        bH[j][1] = sw[w0 + 4];
                bL[j][0] = sw[2560 + w0]; bL[j][1] = sw[2560 + w0 + 4];
            }
#pragma unroll
            for (int i = 0; i < 4; ++i)
#pragma unroll
                for (int j = 0; j < 4; ++j)
                    mma_fp16(acc[i][j], aH[i], bH[j]);
#pragma unroll
            for (int i = 0; i < 4; ++i)
#pragma unroll
                for (int j = 0; j < 4; ++j)
                    mma_fp16(acc[i][j], aH[i], bL[j]);
            if (TERMS == 3) {
#pragma unroll
                for (int i = 0; i < 4; ++i)
#pragma unroll
                    for (int j = 0; j < 4; ++j)
                        mma_fp16(acc[i][j], aL[i], bH[j]);
            }
        }

        if (more) store_tile(smh + ((it + 1) & 1) * STAGE_H);
        __syncthreads();
    }

#pragma unroll
    for (int i = 0; i < 4; ++i) {
        const long r0 = row0 + wm + i * 16 + grp;
#pragma unroll
        for (int j = 0; j < 4; ++j) {
            const long gc = col0 + wn + j * 8 + tig * 2;
            float x0 = acc[i][j][0] * scale, x1 = acc[i][j][1] * scale;
            float y0 = acc[i][j][2] * scale, y1 = acc[i][j][3] * scale;
            if (mask) {
                const bool m0 = mask[gc] != 0, m1 = mask[gc + 1] != 0;
                if (m0) { x0 = -FLT_MAX; y0 = -FLT_MAX; }
                if (m1) { x1 = -FLT_MAX; y1 = -FLT_MAX; }
            }
            *reinterpret_cast<float2*>(C + r0 * ldc + gc)       = make_float2(x0, x1);
            *reinterpret_cast<float2*>(C + (r0 + 8) * ldc + gc) = make_float2(y0, y1);
        }
    }
}

// ---------------------------------------------------------------------------
// Pure fp16 NN GEMM (Z = alpha * H), ldmatrix fragments, cp.async 3-stage.
// A: [M,K] half row-major (alpha), B: [K,N] half row-major (H), C fp32.
// ---------------------------------------------------------------------------
#define ZSTAGE_H 9472
#define ZNSTAGE 3
#define SMEM_Z (ZNSTAGE * ZSTAGE_H * 2)   // 56832 bytes

__global__ __launch_bounds__(256)
void fp16_gemm_nn(const __half* __restrict__ A, const __half* __restrict__ B,
                  float* __restrict__ C,
                  int K, long lda, long ldb, long ldc,
                  long sA, long sB, long sC)
{
    extern __shared__ __align__(16) __half smz[];

    const int tid  = threadIdx.x;
    const int wid  = tid >> 5;
    const int lane = tid & 31;
    const int grp  = lane >> 2;
    const int tig  = lane & 3;
    const int wm   = (wid & 1) * 64;
    const int wn   = (wid >> 1) * 32;

    const int bz = blockIdx.z;
    A += (long)bz * sA;
    B += (long)bz * sB;
    C += (long)bz * sC;

    const long row0 = (long)blockIdx.y * 128;
    const long col0 = (long)blockIdx.x * 128;
    const int nIter = K >> 5;

    const uint32_t aoff = (uint32_t)((wm + (lane & 15)) * 40 + 8 * (lane >> 4));
    const uint32_t boff = (uint32_t)(5120 + (lane & 15) * 136 + wn + 8 * (lane >> 4));

    const uint32_t smz_base = (uint32_t)__cvta_generic_to_shared(smz);

    auto issue_stage = [&](int it) {
        __half* sa = smz + (it % ZNSTAGE) * ZSTAGE_H;
        __half* sb = sa + 5120;
        const __half* pA = A + row0 * lda + (long)it * 32;
#pragma unroll
        for (int p = 0; p < 2; ++p) {
            const int f = p * 256 + tid;
            const int m = f >> 2, kc = (f & 3) * 8;
            cp16(sa + m * 40 + kc, pA + (long)m * lda + kc);
        }
        const __half* pB = B + (long)it * 32 * ldb + col0;
#pragma unroll
        for (int p = 0; p < 2; ++p) {
            const int f = p * 256 + tid;
            const int k = f >> 4, nc = (f & 15) * 8;
            cp16(sb + k * 136 + nc, pB + (long)k * ldb + nc);
        }
    };

    float acc[4][4][4];
#pragma unroll
    for (int i = 0; i < 4; ++i)
#pragma unroll
        for (int j = 0; j < 4; ++j)
#pragma unroll
            for (int r = 0; r < 4; ++r) acc[i][j][r] = 0.0f;

    issue_stage(0); CP_COMMIT();
    issue_stage(1); CP_COMMIT();

    for (int it = 0; it < nIter; ++it) {
        CP_WAIT1();
        __syncthreads();

        if (it + 2 < nIter) issue_stage(it + 2);
        CP_COMMIT();

        const uint32_t stb = smz_base + (uint32_t)((it % ZNSTAGE) * ZSTAGE_H) * 2;

#pragma unroll
        for (int s = 0; s < 2; ++s) {
            uint32_t aF[4][4], bF[2][4];
#pragma unroll
            for (int i = 0; i < 4; ++i)
                ldsm_x4(aF[i], stb + (aoff + i * 16 * 40 + s * 16) * 2);
#pragma unroll
            for (int jp = 0; jp < 2; ++jp)
                ldsm_x4_t(bF[jp], stb + (boff + s * 16 * 136 + jp * 16) * 2);
#pragma unroll
            for (int i = 0; i < 4; ++i) {
#pragma unroll
                for (int jp = 0; jp < 2; ++jp) {
                    mma_fp16(acc[i][2 * jp + 0], aF[i], &bF[jp][0]);
                    mma_fp16(acc[i][2 * jp + 1], aF[i], &bF[jp][2]);
                }
            }
        }
        __syncthreads();
    }

#pragma unroll
    for (int i = 0; i < 4; ++i) {
        const long r0 = row0 + wm + i * 16 + grp;
#pragma unroll
        for (int j = 0; j < 4; ++j) {
            const long gc = col0 + wn + j * 8 + tig * 2;
            *reinterpret_cast<float2*>(C + r0 * ldc + gc) =
                make_float2(acc[i][j][0], acc[i][j][1]);
            *reinterpret_cast<float2*>(C + (r0 + 8) * ldc + gc) =
                make_float2(acc[i][j][2], acc[i][j][3]);
        }
    }
}

// ---------------------------------------------------------------------------
// H -> fp16 conversion (one-shot)
// ---------------------------------------------------------------------------
__global__ __launch_bounds__(256)
void h2half_kernel(const float* __restrict__ X, __half* __restrict__ Y, long n4)
{
    const long i = (long)blockIdx.x * 256 + threadIdx.x;
    if (i < n4) {
        float4 v = reinterpret_cast<const float4*>(X)[i];
        uint2 o;
        o.x = h2_u32(__floats2half2_rn(v.x, v.y));
        o.y = h2_u32(__floats2half2_rn(v.z, v.w));
        reinterpret_cast<uint2*>(Y)[i] = o;
    }
}

// ---------------------------------------------------------------------------
// Row softmax over LL; fp32 logits in, fp16 alpha out. Clock probe ~20 us.
// ---------------------------------------------------------------------------
__global__ __launch_bounds__(256)
void softmax_kernel(const float* __restrict__ S, __half* __restrict__ Ah)
{
    __shared__ float4 buf[LL / 4];
    __shared__ float red[256];

    const int tid = threadIdx.x;
    const float4* p = reinterpret_cast<const float4*>(S + (long)blockIdx.x * LL);
    uint2* out = reinterpret_cast<uint2*>(Ah + (long)blockIdx.x * LL);

    float m = -FLT_MAX;
#pragma unroll
    for (int i = tid; i < LL / 4; i += 256) {
        float4 v = p[i];
        buf[i] = v;
        m = fmaxf(m, fmaxf(fmaxf(v.x, v.y), fmaxf(v.z, v.w)));
    }
    red[tid] = m;
    __syncthreads();
    for (int s = 128; s > 0; s >>= 1) {
        if (tid < s) red[tid] = fmaxf(red[tid], red[tid + s]);
        __syncthreads();
    }
    m = red[0];
    __syncthreads();

    float sum = 0.0f;
#pragma unroll
    for (int i = tid; i < LL / 4; i += 256) {
        float4 v = buf[i];
        v.x = __expf(v.x - m); v.y = __expf(v.y - m);
        v.z = __expf(v.z - m); v.w = __expf(v.w - m);
        buf[i] = v;
        sum += v.x + v.y + v.z + v.w;
    }
    red[tid] = sum;
    __syncthreads();
    for (int s = 128; s > 0; s >>= 1) {
        if (tid < s) red[tid] += red[tid + s];
        __syncthreads();
    }
    const float inv = 1.0f / red[0];

#pragma unroll
    for (int i = tid; i < LL / 4; i += 256) {
        float4 v = buf[i];
        uint2 o;
        o.x = h2_u32(__floats2half2_rn(v.x * inv, v.y * inv));
        o.y = h2_u32(__floats2half2_rn(v.z * inv, v.w * inv));
        out[i] = o;
    }
}

// ---------------------------------------------------------------------------
// Launch. Inputs: H [B,L,DH] f32, G [B,T,DG] f32, mask [B,L] int32,
// Wk_w [P,DH] f32, Wq_w [P,DG] f32. Output Z [B,T,DH] f32.
// ---------------------------------------------------------------------------
extern "C" void kernel_launch(void* const* d_in, const int* in_sizes, int n_in,
                              void* d_out, int out_size)
{
    const float* H    = (const float*)d_in[0];
    const float* G    = (const float*)d_in[1];
    const int*   mask = (const int*)d_in[2];
    const float* Wk   = (const float*)d_in[3];
    const float* Wq   = (const float*)d_in[4];
    float*       Z    = (float*)d_out;

    float  *gK, *gQ, *gS;
    __half *gAh, *gHh;
    cudaGetSymbolAddress((void**)&gK,  g_K);
    cudaGetSymbolAddress((void**)&gQ,  g_Q);
    cudaGetSymbolAddress((void**)&gS,  g_S);
    cudaGetSymbolAddress((void**)&gAh, g_Ah);
    cudaGetSymbolAddress((void**)&gHh, g_Hh);

    cudaFuncSetAttribute(fp16x3_gemm_nt<3>,
                         cudaFuncAttributeMaxDynamicSharedMemorySize, SMEM_GEMM);
    cudaFuncSetAttribute(fp16x3_gemm_nt<2>,
                         cudaFuncAttributeMaxDynamicSharedMemorySize, SMEM_GEMM);
    cudaFuncSetAttribute(fp16_gemm_nn,
                         cudaFuncAttributeMaxDynamicSharedMemorySize, SMEM_Z);

    // 0) H -> fp16 (for the Z GEMM B-operand)
    {
        const long n4 = (long)BB * LL * DHQ / 4;
        h2half_kernel<<<(unsigned)((n4 + 255) / 256), 256>>>(H, gHh, n4);
    }

    // 1) K = H * Wk^T (2-term: H fp16-quantized, Wk exact to 22 bits)
    fp16x3_gemm_nt<2><<<dim3(PPQ / 128, (BB * LL) / 128, 1), 256, SMEM_GEMM>>>(
        H, Wk, gK, DHQ, DHQ, DHQ, PPQ, 0, 0, 0, 1.0f, nullptr, 0);

    // 2) Q = G * Wq^T (3-term — cheap insurance on the query path)
    fp16x3_gemm_nt<3><<<dim3(PPQ / 128, (BB * TTQ) / 128, 1), 256, SMEM_GEMM>>>(
        G, Wq, gQ, DGQ, DGQ, DGQ, PPQ, 0, 0, 0, 1.0f, nullptr, 0);

    // 3) S = scale * Q * K^T (masked; 2-term: Q fp16-quantized, K exact)
    fp16x3_gemm_nt<2><<<dim3(LL / 128, TTQ / 128, BB), 256, SMEM_GEMM>>>(
        gQ, gK, gS, PPQ, PPQ, PPQ, LL,
        (long)TTQ * PPQ, (long)LL * PPQ, (long)TTQ * LL,
        0.0625f, mask, (long)LL);

    // 4) softmax over L, emitting fp16 alpha
    softmax_kernel<<<BB * TTQ, 256>>>(gS, gAh);

    // 5) Z = alpha_h * H_h (pure fp16)
    fp16_gemm_nn<<<dim3(DHQ / 128, TTQ / 128, BB), 256, SMEM_Z>>>(
        gAh, gHh, Z, LL, LL, DHQ, DHQ,
        (long)TTQ * LL, (long)LL * DHQ, (long)TTQ * DHQ);
}

// round 16
// speedup vs baseline: 2.9845x; 1.3929x over previous
#include <cuda_runtime.h>
#include <cuda_fp16.h>
#include <cstdint>
#include <float.h>

// Problem constants
#define BB 4
#define LL 4096
#define DHQ 1024
#define TTQ 1024
#define DGQ 768
#define PPQ 256

// Scratch (__device__ globals; no cudaMalloc allowed)
__device__ float  g_K [(size_t)BB * LL  * PPQ];  // 16 MB  compacted K
__device__ float  g_Q [(size_t)BB * TTQ * PPQ];  //  4 MB
__device__ float  g_S [(size_t)BB * TTQ * LL ];  // 64 MB  compacted-col logits
__device__ __half g_Ah[(size_t)BB * TTQ * LL ];  // 32 MB  compacted alpha (fp16)
__device__ __half g_Hh[(size_t)BB * LL  * DHQ];  // 32 MB  compacted H (fp16)
__device__ int    g_vidx[(size_t)BB * LL];       // valid key indices per batch
__device__ int    g_Lv[BB];                      // valid count per batch

// ---------------------------------------------------------------------------
// helpers
// ---------------------------------------------------------------------------
__device__ __forceinline__ void mma_fp16(float* d, const uint32_t* a, const uint32_t* b) {
    asm volatile(
        "mma.sync.aligned.m16n8k16.row.col.f32.f16.f16.f32 "
        "{%0,%1,%2,%3}, {%4,%5,%6,%7}, {%8,%9}, {%0,%1,%2,%3};"
        : "+f"(d[0]), "+f"(d[1]), "+f"(d[2]), "+f"(d[3])
        : "r"(a[0]), "r"(a[1]), "r"(a[2]), "r"(a[3]), "r"(b[0]), "r"(b[1]));
}

__device__ __forceinline__ uint32_t h2_u32(__half2 h) {
    return *reinterpret_cast<uint32_t*>(&h);
}

__device__ __forceinline__ void split2(float x, float y, uint32_t& hi, uint32_t& lo) {
    __half2 h = __floats2half2_rn(x, y);
    float2 hb = __half22float2(h);
    __half2 l = __floats2half2_rn(x - hb.x, y - hb.y);
    hi = h2_u32(h);
    lo = h2_u32(l);
}

__device__ __forceinline__ void cp16(void* sdst, const void* gsrc) {
    uint32_t a = (uint32_t)__cvta_generic_to_shared(sdst);
    asm volatile("cp.async.cg.shared.global [%0], [%1], 16;" :: "r"(a), "l"(gsrc));
}
#define CP_COMMIT() asm volatile("cp.async.commit_group;" ::: "memory")
#define CP_WAIT1()  asm volatile("cp.async.wait_group 1;" ::: "memory")

__device__ __forceinline__ void ldsm_x4(uint32_t* r, uint32_t saddr) {
    asm volatile("ldmatrix.sync.aligned.m8n8.x4.shared.b16 {%0,%1,%2,%3}, [%4];"
                 : "=r"(r[0]), "=r"(r[1]), "=r"(r[2]), "=r"(r[3]) : "r"(saddr));
}
__device__ __forceinline__ void ldsm_x4_t(uint32_t* r, uint32_t saddr) {
    asm volatile("ldmatrix.sync.aligned.m8n8.x4.trans.shared.b16 {%0,%1,%2,%3}, [%4];"
                 : "=r"(r[0]), "=r"(r[1]), "=r"(r[2]), "=r"(r[3]) : "r"(saddr));
}

// ---------------------------------------------------------------------------
// Mask compaction: per batch, ascending list of valid key indices + count.
// mask[b][l] nonzero = masked. One block of 1024 threads per batch.
// vidx entries beyond Lv are set to 0 (safe dummy row for gather padding).
// ---------------------------------------------------------------------------
__global__ __launch_bounds__(1024)
void compact_kernel(const int* __restrict__ mask, int* __restrict__ vidx,
                    int* __restrict__ LvArr)
{
    __shared__ int ssum[1024];
    const int b = blockIdx.x;
    const int t = threadIdx.x;
    const int4 mv = reinterpret_cast<const int4*>(mask + (long)b * LL)[t];
    const int f0 = (mv.x == 0), f1 = (mv.y == 0), f2 = (mv.z == 0), f3 = (mv.w == 0);
    const int s = f0 + f1 + f2 + f3;
    ssum[t] = s;
    __syncthreads();
    // inclusive Hillis-Steele scan
    for (int off = 1; off < 1024; off <<= 1) {
        int v = (t >= off) ? ssum[t - off] : 0;
        __syncthreads();
        ssum[t] += v;
        __syncthreads();
    }
    const int Lv = ssum[1023];
    int pos = ssum[t] - s;
    const int j = t * 4;
    int* vb = vidx + (long)b * LL;
    if (f0) vb[pos++] = j;
    if (f1) vb[pos++] = j + 1;
    if (f2) vb[pos++] = j + 2;
    if (f3) vb[pos++] = j + 3;
    if (t == 0) LvArr[b] = Lv;
    for (int q = Lv + t; q < LL; q += 1024) vb[q] = 0;
}

// ---------------------------------------------------------------------------
// Gather + fp16-convert H into compacted order: Hc[b][j] = half(H[b][vidx[j]])
// for j < Lv; zero rows for j in [Lv, Lpad). Grid (32, BB), 256 threads.
// ---------------------------------------------------------------------------
__global__ __launch_bounds__(256)
void gather_h_kernel(const float* __restrict__ H, const int* __restrict__ vidx,
                     const int* __restrict__ LvArr, __half* __restrict__ Hc)
{
    const int b = blockIdx.y;
    const int Lv = LvArr[b];
    const int Lpad = (Lv + 127) & ~127;
    const int j0 = blockIdx.x * 128;
    if (j0 >= Lpad) return;
    const int* vx = vidx + (long)b * LL;
    const float* Hb = H + (size_t)b * LL * DHQ;
    __half* Hcb = Hc + (size_t)b * LL * DHQ;

    for (int idx = threadIdx.x; idx < 128 * 128; idx += 256) {
        const int r = idx >> 7;          // row within block tile
        const int seg = idx & 127;       // 8-half segment within row
        const int j = j0 + r;
        if (j >= Lpad) continue;
        uint4 o;
        if (j < Lv) {
            const float4* src = reinterpret_cast<const float4*>(
                Hb + (size_t)vx[j] * DHQ + seg * 8);
            float4 a = src[0], c = src[1];
            o.x = h2_u32(__floats2half2_rn(a.x, a.y));
            o.y = h2_u32(__floats2half2_rn(a.z, a.w));
            o.z = h2_u32(__floats2half2_rn(c.x, c.y));
            o.w = h2_u32(__floats2half2_rn(c.z, c.w));
        } else {
            o = make_uint4(0, 0, 0, 0);
        }
        *reinterpret_cast<uint4*>(Hcb + (size_t)j * DHQ + seg * 8) = o;
    }
}

// ---------------------------------------------------------------------------
// fp16 split NT GEMM: C[M,N] = scale * A[M,K] * B[N,K]^T
//   TERMS=3: aH*bH + aH*bL + aL*bH;  TERMS=2: aH*bH + aH*bL
//   GATHER: A rows gathered through vidx (compacted K-proj); exit row0>=Lv
//   EXITC : skip tiles with col0 >= Lv (compacted logits columns)
// Block tile 128x128, BK=32, 256 threads (8 warps, 64x32 warp tiles).
// ---------------------------------------------------------------------------
#define STAGE_H 20480
#define SMEM_GEMM (2 * STAGE_H * 2)   // 81920 bytes

template <int TERMS, bool GATHER, bool EXITC>
__global__ __launch_bounds__(256)
void fp16x3_gemm_nt(const float* __restrict__ A, const float* __restrict__ B,
                    float* __restrict__ C,
                    int K, long lda, long ldb, long ldc,
                    long sA, long sB, long sC, float scale,
                    const int* __restrict__ vidx, const int* __restrict__ LvArr)
{
    extern __shared__ __align__(16) uint16_t smh[];

    const int tid  = threadIdx.x;
    const int wid  = tid >> 5;
    const int lane = tid & 31;
    const int grp  = lane >> 2;
    const int tig  = lane & 3;
    const int wm   = (wid & 1) * 64;
    const int wn   = (wid >> 1) * 32;

    const int bz = blockIdx.z;
    const long row0 = (long)blockIdx.y * 128;
    const long col0 = (long)blockIdx.x * 128;

    if (GATHER || EXITC) {
        const int Lv = LvArr[bz];
        if (GATHER && row0 >= Lv) return;
        if (EXITC && col0 >= Lv) return;
    }

    A += (long)bz * sA;
    B += (long)bz * sB;
    C += (long)bz * sC;

    // Hoist per-thread row pointers (gather indices constant across k-loop)
    const float* aRow[4];
    const float* bRow[4];
#pragma unroll
    for (int p = 0; p < 4; ++p) {
        const int f = p * 256 + tid;
        const int m = (int)row0 + (f >> 3);
        const long ri = GATHER ? (long)vidx[(long)bz * LL + m] : (long)m;
        aRow[p] = A + ri * lda + (f & 7) * 4;
        bRow[p] = B + (col0 + (f >> 3)) * ldb + (f & 7) * 4;
    }

    const int nIter = K >> 5;
    float4 rA[4], rB[4];

    auto load_tile = [&](int it) {
        const long ko = (long)it * 32;
#pragma unroll
        for (int p = 0; p < 4; ++p) rA[p] = *reinterpret_cast<const float4*>(aRow[p] + ko);
#pragma unroll
        for (int p = 0; p < 4; ++p) rB[p] = *reinterpret_cast<const float4*>(bRow[p] + ko);
    };

    auto store_tile = [&](uint16_t* st) {
#pragma unroll
        for (int p = 0; p < 4; ++p) {
            const int f = p * 256 + tid;
            {
                const int m = f >> 3, kc = (f & 7) * 4;
                float4 v = rA[p];
                uint32_t h0, l0, h1, l1;
                split2(v.x, v.y, h0, l0);
                split2(v.z, v.w, h1, l1);
                *reinterpret_cast<uint2*>(st + m * 40 + kc) = make_uint2(h0, h1);
                if (TERMS == 3)
                    *reinterpret_cast<uint2*>(st + 5120 + m * 40 + kc) = make_uint2(l0, l1);
            }
            {
                const int n = f >> 3, kc = (f & 7) * 4;
                float4 v = rB[p];
                uint32_t h0, l0, h1, l1;
                split2(v.x, v.y, h0, l0);
                split2(v.z, v.w, h1, l1);
                *reinterpret_cast<uint2*>(st + 10240 + n * 40 + kc) = make_uint2(h0, h1);
                *reinterpret_cast<uint2*>(st + 15360 + n * 40 + kc) = make_uint2(l0, l1);
            }
        }
    };

    float acc[4][4][4];
#pragma unroll
    for (int i = 0; i < 4; ++i)
#pragma unroll
        for (int j = 0; j < 4; ++j)
#pragma unroll
            for (int r = 0; r < 4; ++r) acc[i][j][r] = 0.0f;

    load_tile(0);
    store_tile(smh);
    __syncthreads();

    for (int it = 0; it < nIter; ++it) {
        const bool more = (it + 1 < nIter);
        if (more) load_tile(it + 1);

        const uint32_t* sw = reinterpret_cast<const uint32_t*>(smh + (it & 1) * STAGE_H);

#pragma unroll
        for (int ks = 0; ks < 2; ++ks) {
            uint32_t aH[4][4], aL[4][4], bH[4][2], bL[4][2];
#pragma unroll
            for (int i = 0; i < 4; ++i) {
                const int r  = wm + i * 16 + grp;
                const int w0 = r * 20 + tig + 8 * ks;
                const int w1 = (r + 8) * 20 + tig + 8 * ks;
                aH[i][0] = sw[w0];     aH[i][1] = sw[w1];
                aH[i][2] = sw[w0 + 4]; aH[i][3] = sw[w1 + 4];
                if (TERMS == 3) {
                    aL[i][0] = sw[2560 + w0];     aL[i][1] = sw[2560 + w1];
                    aL[i][2] = sw[2560 + w0 + 4]; aL[i][3] = sw[2560 + w1 + 4];
                }
            }
#pragma unroll
            for (int j = 0; j < 4; ++j) {
                const int n  = wn + j * 8 + grp;
                const int w0 = 5120 + n * 20 + tig + 8 * ks;
                bH[j][0] = sw[w0];        bH[j][1] = sw[w0 + 4];
                bL[j][0] = sw[2560 + w0]; bL[j][1] = sw[2560 + w0 + 4];
            }
#pragma unroll
            for (int i = 0; i < 4; ++i)
#pragma unroll
                for (int j = 0; j < 4; ++j)
                    mma_fp16(acc[i][j], aH[i], bH[j]);
#pragma unroll
            for (int i = 0; i < 4; ++i)
#pragma unroll
                for (int j = 0; j < 4; ++j)
                    mma_fp16(acc[i][j], aH[i], bL[j]);
            if (TERMS == 3) {
#pragma unroll
                for (int i = 0; i < 4; ++i)
#pragma unroll
                    for (int j = 0; j < 4; ++j)
                        mma_fp16(acc[i][j], aL[i], bH[j]);
            }
        }

        if (more) store_tile(smh + ((it + 1) & 1) * STAGE_H);
        __syncthreads();
    }

#pragma unroll
    for (int i = 0; i < 4; ++i) {
        const long r0 = row0 + wm + i * 16 + grp;
#pragma unroll
        for (int j = 0; j < 4; ++j) {
            const long gc = col0 + wn + j * 8 + tig * 2;
            *reinterpret_cast<float2*>(C + r0 * ldc + gc) =
                make_float2(acc[i][j][0] * scale, acc[i][j][1] * scale);
            *reinterpret_cast<float2*>(C + (r0 + 8) * ldc + gc) =
                make_float2(acc[i][j][2] * scale, acc[i][j][3] * scale);
        }
    }
}

// ---------------------------------------------------------------------------
// Pure fp16 NN GEMM (Z = alpha_c * H_c), variable compacted K per batch.
// A: [M,4096] half (alpha, zero-padded to Lpad), B: [4096,N] half, C fp32.
// ---------------------------------------------------------------------------
#define ZSTAGE_H 9472
#define ZNSTAGE 3
#define SMEM_Z (ZNSTAGE * ZSTAGE_H * 2)   // 56832 bytes

__global__ __launch_bounds__(256)
void fp16_gemm_nn(const __half* __restrict__ A, const __half* __restrict__ B,
                  float* __restrict__ C,
                  long lda, long ldb, long ldc,
                  long sA, long sB, long sC, const int* __restrict__ LvArr)
{
    extern __shared__ __align__(16) __half smz[];

    const int tid  = threadIdx.x;
    const int wid  = tid >> 5;
    const int lane = tid & 31;
    const int grp  = lane >> 2;
    const int tig  = lane & 3;
    const int wm   = (wid & 1) * 64;
    const int wn   = (wid >> 1) * 32;

    const int bz = blockIdx.z;
    const int Lv = LvArr[bz];
    const int nIter = ((Lv + 127) & ~127) >> 5;

    A += (long)bz * sA;
    B += (long)bz * sB;
    C += (long)bz * sC;

    const long row0 = (long)blockIdx.y * 128;
    const long col0 = (long)blockIdx.x * 128;

    const uint32_t aoff = (uint32_t)((wm + (lane & 15)) * 40 + 8 * (lane >> 4));
    const uint32_t boff = (uint32_t)(5120 + (lane & 15) * 136 + wn + 8 * (lane >> 4));

    const uint32_t smz_base = (uint32_t)__cvta_generic_to_shared(smz);

    auto issue_stage = [&](int it) {
        __half* sa = smz + (it % ZNSTAGE) * ZSTAGE_H;
        __half* sb = sa + 5120;
        const __half* pA = A + row0 * lda + (long)it * 32;
#pragma unroll
        for (int p = 0; p < 2; ++p) {
            const int f = p * 256 + tid;
            const int m = f >> 2, kc = (f & 3) * 8;
            cp16(sa + m * 40 + kc, pA + (long)m * lda + kc);
        }
        const __half* pB = B + (long)it * 32 * ldb + col0;
#pragma unroll
        for (int p = 0; p < 2; ++p) {
            const int f = p * 256 + tid;
            const int k = f >> 4, nc = (f & 15) * 8;
            cp16(sb + k * 136 + nc, pB + (long)k * ldb + nc);
        }
    };

    float acc[4][4][4];
#pragma unroll
    for (int i = 0; i < 4; ++i)
#pragma unroll
        for (int j = 0; j < 4; ++j)
#pragma unroll
            for (int r = 0; r < 4; ++r) acc[i][j][r] = 0.0f;

    issue_stage(0); CP_COMMIT();
    issue_stage(1); CP_COMMIT();

    for (int it = 0; it < nIter; ++it) {
        CP_WAIT1();
        __syncthreads();

        if (it + 2 < nIter) issue_stage(it + 2);
        CP_COMMIT();

        const uint32_t stb = smz_base + (uint32_t)((it % ZNSTAGE) * ZSTAGE_H) * 2;

#pragma unroll
        for (int s = 0; s < 2; ++s) {
            uint32_t aF[4][4], bF[2][4];
#pragma unroll
            for (int i = 0; i < 4; ++i)
                ldsm_x4(aF[i], stb + (aoff + i * 16 * 40 + s * 16) * 2);
#pragma unroll
            for (int jp = 0; jp < 2; ++jp)
                ldsm_x4_t(bF[jp], stb + (boff + s * 16 * 136 + jp * 16) * 2);
#pragma unroll
            for (int i = 0; i < 4; ++i) {
#pragma unroll
                for (int jp = 0; jp < 2; ++jp) {
                    mma_fp16(acc[i][2 * jp + 0], aF[i], &bF[jp][0]);
                    mma_fp16(acc[i][2 * jp + 1], aF[i], &bF[jp][2]);
                }
            }
        }
        __syncthreads();
    }

#pragma unroll
    for (int i = 0; i < 4; ++i) {
        const long r0 = row0 + wm + i * 16 + grp;
#pragma unroll
        for (int j = 0; j < 4; ++j) {
            const long gc = col0 + wn + j * 8 + tig * 2;
            *reinterpret_cast<float2*>(C + r0 * ldc + gc) =
                make_float2(acc[i][j][0], acc[i][j][1]);
            *reinterpret_cast<float2*>(C + (r0 + 8) * ldc + gc) =
                make_float2(acc[i][j][2], acc[i][j][3]);
        }
    }
}

// ---------------------------------------------------------------------------
// Length-aware row softmax over compacted columns; fp32 logits in, fp16 alpha
// out (zeros written on [Lv, Lpad) so Z's padded K-loop is exact).
// ---------------------------------------------------------------------------
__global__ __launch_bounds__(256)
void softmax_kernel(const float* __restrict__ S, __half* __restrict__ Ah,
                    const int* __restrict__ LvArr)
{
    __shared__ float4 buf[LL / 4];
    __shared__ float red[256];

    const int tid = threadIdx.x;
    const int b = blockIdx.x >> 10;           // TTQ = 1024 rows per batch
    const int Lv = LvArr[b];
    const int L4 = ((Lv + 127) & ~127) >> 2;  // Lpad / 4

    const float4* p = reinterpret_cast<const float4*>(S + (long)blockIdx.x * LL);
    uint2* out = reinterpret_cast<uint2*>(Ah + (long)blockIdx.x * LL);

    float m = -FLT_MAX;
    for (int i = tid; i < L4; i += 256) {
        float4 v = p[i];
        const int j = i * 4;
        if (j     >= Lv) v.x = -1e30f;
        if (j + 1 >= Lv) v.y = -1e30f;
        if (j + 2 >= Lv) v.z = -1e30f;
        if (j + 3 >= Lv) v.w = -1e30f;
        buf[i] = v;
        m = fmaxf(m, fmaxf(fmaxf(v.x, v.y), fmaxf(v.z, v.w)));
    }
    red[tid] = m;
    __syncthreads();
    for (int s = 128; s > 0; s >>= 1) {
        if (tid < s) red[tid] = fmaxf(red[tid], red[tid + s]);
        __syncthreads();
    }
    m = red[0];
    __syncthreads();

    float sum = 0.0f;
    for (int i = tid; i < L4; i += 256) {
        float4 v = buf[i];
        v.x = __expf(v.x - m); v.y = __expf(v.y - m);
        v.z = __expf(v.z - m); v.w = __expf(v.w - m);
        buf[i] = v;
        sum += v.x + v.y + v.z + v.w;
    }
    red[tid] = sum;
    __syncthreads();
    for (int s = 128; s > 0; s >>= 1) {
        if (tid < s) red[tid] += red[tid + s];
        __syncthreads();
    }
    const float inv = 1.0f / red[0];

    for (int i = tid; i < L4; i += 256) {
        float4 v = buf[i];
        uint2 o;
        o.x = h2_u32(__floats2half2_rn(v.x * inv, v.y * inv));
        o.y = h2_u32(__floats2half2_rn(v.z * inv, v.w * inv));
        out[i] = o;
    }
}

// ---------------------------------------------------------------------------
// Launch. Inputs: H [B,L,DH] f32, G [B,T,DG] f32, mask [B,L] int32,
// Wk_w [P,DH] f32, Wq_w [P,DG] f32. Output Z [B,T,DH] f32.
// ---------------------------------------------------------------------------
extern "C" void kernel_launch(void* const* d_in, const int* in_sizes, int n_in,
                              void* d_out, int out_size)
{
    const float* H    = (const float*)d_in[0];
    const float* G    = (const float*)d_in[1];
    const int*   mask = (const int*)d_in[2];
    const float* Wk   = (const float*)d_in[3];
    const float* Wq   = (const float*)d_in[4];
    float*       Z    = (float*)d_out;

    float  *gK, *gQ, *gS;
    __half *gAh, *gHh;
    int *gVidx, *gLv;
    cudaGetSymbolAddress((void**)&gK,   g_K);
    cudaGetSymbolAddress((void**)&gQ,   g_Q);
    cudaGetSymbolAddress((void**)&gS,   g_S);
    cudaGetSymbolAddress((void**)&gAh,  g_Ah);
    cudaGetSymbolAddress((void**)&gHh,  g_Hh);
    cudaGetSymbolAddress((void**)&gVidx, g_vidx);
    cudaGetSymbolAddress((void**)&gLv,  g_Lv);

    cudaFuncSetAttribute((const void*)fp16x3_gemm_nt<3, false, false>,
                         cudaFuncAttributeMaxDynamicSharedMemorySize, SMEM_GEMM);
    cudaFuncSetAttribute((const void*)fp16x3_gemm_nt<2, true, false>,
                         cudaFuncAttributeMaxDynamicSharedMemorySize, SMEM_GEMM);
    cudaFuncSetAttribute((const void*)fp16x3_gemm_nt<2, false, true>,
                         cudaFuncAttributeMaxDynamicSharedMemorySize, SMEM_GEMM);
    cudaFuncSetAttribute((const void*)fp16_gemm_nn,
                         cudaFuncAttributeMaxDynamicSharedMemorySize, SMEM_Z);

    // 0a) build compacted valid-key index lists
    compact_kernel<<<BB, 1024>>>(mask, gVidx, gLv);

    // 0b) gather + fp16-convert H rows into compacted order (Z B-operand)
    gather_h_kernel<<<dim3(32, BB), 256>>>(H, gVidx, gLv, gHh);

    // 1) Kc = gather(H) * Wk^T (2-term), compacted rows per batch
    fp16x3_gemm_nt<2, true, false><<<dim3(PPQ / 128, 32, BB), 256, SMEM_GEMM>>>(
        H, Wk, gK, DHQ, DHQ, DHQ, PPQ,
        (long)LL * DHQ, 0, (long)LL * PPQ, 1.0f, gVidx, gLv);

    // 2) Q = G * Wq^T (3-term, full)
    fp16x3_gemm_nt<3, false, false><<<dim3(PPQ / 128, 32, 1), 256, SMEM_GEMM>>>(
        G, Wq, gQ, DGQ, DGQ, DGQ, PPQ, 0, 0, 0, 1.0f, nullptr, nullptr);

    // 3) S = scale * Q * Kc^T over compacted columns (2-term; no mask needed)
    fp16x3_gemm_nt<2, false, true><<<dim3(32, TTQ / 128, BB), 256, SMEM_GEMM>>>(
        gQ, gK, gS, PPQ, PPQ, PPQ, LL,
        (long)TTQ * PPQ, (long)LL * PPQ, (long)TTQ * LL, 0.0625f, nullptr, gLv);

    // 4) length-aware softmax, emitting zero-padded fp16 alpha
    softmax_kernel<<<BB * TTQ, 256>>>(gS, gAh, gLv);

    // 5) Z = alpha_c * Hc over compacted K (pure fp16, variable nIter)
    fp16_gemm_nn<<<dim3(DHQ / 128, TTQ / 128, BB), 256, SMEM_Z>>>(
        gAh, gHh, Z, LL, DHQ, DHQ,
        (long)TTQ * LL, (long)LL * DHQ, (long)TTQ * DHQ, gLv);
}

// round 17
// speedup vs baseline: 3.1994x; 1.0720x over previous
#include <cuda_runtime.h>
#include <cuda_fp16.h>
#include <cstdint>
#include <float.h>

// Problem constants
#define BB 4
#define LL 4096
#define DHQ 1024
#define TTQ 1024
#define DGQ 768
#define PPQ 256

// Scratch (__device__ globals; no cudaMalloc allowed)
__device__ float  g_K [(size_t)BB * LL  * PPQ];  // 16 MB  compacted K
__device__ float  g_Q [(size_t)BB * TTQ * PPQ];  //  4 MB
__device__ float  g_S [(size_t)BB * TTQ * LL ];  // 64 MB  compacted-col logits
__device__ __half g_Ah[(size_t)BB * TTQ * LL ];  // 32 MB  compacted alpha (fp16)
__device__ __half g_Hh[(size_t)BB * LL  * DHQ];  // 32 MB  compacted H (fp16)
__device__ int    g_vidx[(size_t)BB * LL];       // valid key indices per batch
__device__ int    g_Lv[BB];                      // valid count per batch

// ---------------------------------------------------------------------------
// helpers
// ---------------------------------------------------------------------------
__device__ __forceinline__ void mma_fp16(float* d, const uint32_t* a, const uint32_t* b) {
    asm volatile(
        "mma.sync.aligned.m16n8k16.row.col.f32.f16.f16.f32 "
        "{%0,%1,%2,%3}, {%4,%5,%6,%7}, {%8,%9}, {%0,%1,%2,%3};"
        : "+f"(d[0]), "+f"(d[1]), "+f"(d[2]), "+f"(d[3])
        : "r"(a[0]), "r"(a[1]), "r"(a[2]), "r"(a[3]), "r"(b[0]), "r"(b[1]));
}

__device__ __forceinline__ uint32_t h2_u32(__half2 h) {
    return *reinterpret_cast<uint32_t*>(&h);
}

__device__ __forceinline__ void split2(float x, float y, uint32_t& hi, uint32_t& lo) {
    __half2 h = __floats2half2_rn(x, y);
    float2 hb = __half22float2(h);
    __half2 l = __floats2half2_rn(x - hb.x, y - hb.y);
    hi = h2_u32(h);
    lo = h2_u32(l);
}

__device__ __forceinline__ void cp16(void* sdst, const void* gsrc) {
    uint32_t a = (uint32_t)__cvta_generic_to_shared(sdst);
    asm volatile("cp.async.cg.shared.global [%0], [%1], 16;" :: "r"(a), "l"(gsrc));
}
#define CP_COMMIT() asm volatile("cp.async.commit_group;" ::: "memory")
#define CP_WAIT1()  asm volatile("cp.async.wait_group 1;" ::: "memory")

__device__ __forceinline__ void ldsm_x4(uint32_t* r, uint32_t saddr) {
    asm volatile("ldmatrix.sync.aligned.m8n8.x4.shared.b16 {%0,%1,%2,%3}, [%4];"
                 : "=r"(r[0]), "=r"(r[1]), "=r"(r[2]), "=r"(r[3]) : "r"(saddr));
}
__device__ __forceinline__ void ldsm_x4_t(uint32_t* r, uint32_t saddr) {
    asm volatile("ldmatrix.sync.aligned.m8n8.x4.trans.shared.b16 {%0,%1,%2,%3}, [%4];"
                 : "=r"(r[0]), "=r"(r[1]), "=r"(r[2]), "=r"(r[3]) : "r"(saddr));
}

// ---------------------------------------------------------------------------
// Mask compaction: per batch, ascending list of valid key indices + count.
// ---------------------------------------------------------------------------
__global__ __launch_bounds__(1024)
void compact_kernel(const int* __restrict__ mask, int* __restrict__ vidx,
                    int* __restrict__ LvArr)
{
    __shared__ int ssum[1024];
    const int b = blockIdx.x;
    const int t = threadIdx.x;
    const int4 mv = reinterpret_cast<const int4*>(mask + (long)b * LL)[t];
    const int f0 = (mv.x == 0), f1 = (mv.y == 0), f2 = (mv.z == 0), f3 = (mv.w == 0);
    const int s = f0 + f1 + f2 + f3;
    ssum[t] = s;
    __syncthreads();
    for (int off = 1; off < 1024; off <<= 1) {
        int v = (t >= off) ? ssum[t - off] : 0;
        __syncthreads();
        ssum[t] += v;
        __syncthreads();
    }
    const int Lv = ssum[1023];
    int pos = ssum[t] - s;
    const int j = t * 4;
    int* vb = vidx + (long)b * LL;
    if (f0) vb[pos++] = j;
    if (f1) vb[pos++] = j + 1;
    if (f2) vb[pos++] = j + 2;
    if (f3) vb[pos++] = j + 3;
    if (t == 0) LvArr[b] = Lv;
    for (int q = Lv + t; q < LL; q += 1024) vb[q] = 0;
}

// ---------------------------------------------------------------------------
// FUSED projection launch. Grid (2, 32, 6), 256 threads, SMEM_GEMM dyn smem.
//   z in [0,4): K-proj batch z — Kc = gather(H) * Wk^T, 2-term, row-exit at Lv
//   z == 4   : Q-proj        — Q  = G * Wq^T, 2-term
//   z == 5   : gather/convert — Hc[b][j] = half(H[b][vidx[j]]), zero pad
// All three are independent; fusing fills the 148-SM chip (256 blocks)
// and hides the memory-bound gather under GEMM compute.
// ---------------------------------------------------------------------------
#define STAGE_H 20480
#define SMEM_GEMM (2 * STAGE_H * 2)   // 81920 bytes

__global__ __launch_bounds__(256)
void fused_proj_kernel(const float* __restrict__ H,  const float* __restrict__ Wk,
                       float* __restrict__ Kc,
                       const float* __restrict__ G,  const float* __restrict__ Wq,
                       float* __restrict__ Qo,
                       const int* __restrict__ vidx, const int* __restrict__ LvArr,
                       __half* __restrict__ Hc)
{
    extern __shared__ __align__(16) uint16_t smh[];

    const int z   = blockIdx.z;
    const int tid = threadIdx.x;

    // ---- z == 5: gather + fp16 convert (64 blocks x 256 rows) ----
    if (z == 5) {
        const int id = blockIdx.y * 2 + blockIdx.x;   // 0..63
        const int b  = id >> 4;
        const int j0 = (id & 15) * 256;
        const int Lv = LvArr[b];
        const int Lpad = (Lv + 127) & ~127;
        if (j0 >= Lpad) return;
        const int* vx = vidx + (long)b * LL;
        const float* Hb = H + (size_t)b * LL * DHQ;
        __half* Hcb = Hc + (size_t)b * LL * DHQ;
        for (int idx = tid; idx < 256 * 128; idx += 256) {
            const int r = idx >> 7;
            const int seg = idx & 127;
            const int j = j0 + r;
            if (j >= Lpad) continue;
            uint4 o;
            if (j < Lv) {
                const float4* src = reinterpret_cast<const float4*>(
                    Hb + (size_t)vx[j] * DHQ + seg * 8);
                float4 a = src[0], c = src[1];
                o.x = h2_u32(__floats2half2_rn(a.x, a.y));
                o.y = h2_u32(__floats2half2_rn(a.z, a.w));
                o.z = h2_u32(__floats2half2_rn(c.x, c.y));
                o.w = h2_u32(__floats2half2_rn(c.z, c.w));
            } else {
                o = make_uint4(0, 0, 0, 0);
            }
            *reinterpret_cast<uint4*>(Hcb + (size_t)j * DHQ + seg * 8) = o;
        }
        return;
    }

    // ---- z < 5: 2-term NT GEMM (K-proj with gather, or Q-proj) ----
    const int wid  = tid >> 5;
    const int lane = tid & 31;
    const int grp  = lane >> 2;
    const int tig  = lane & 3;
    const int wm   = (wid & 1) * 64;
    const int wn   = (wid >> 1) * 32;

    const long row0 = (long)blockIdx.y * 128;
    const long col0 = (long)blockIdx.x * 128;

    const float* A; const float* B; float* C;
    int K; long lda, ldc;
    bool gat; int bz = 0;
    if (z < 4) {
        const int Lv = LvArr[z];
        if (row0 >= Lv) return;
        A = H + (size_t)z * LL * DHQ; B = Wk; C = Kc + (size_t)z * LL * PPQ;
        K = DHQ; lda = DHQ; ldc = PPQ; gat = true; bz = z;
    } else {
        A = G; B = Wq; C = Qo;
        K = DGQ; lda = DGQ; ldc = PPQ; gat = false;
    }
    const long ldb = lda;   // both weight matrices share inner dim with A

    const float* aRow[4];
    const float* bRow[4];
#pragma unroll
    for (int p = 0; p < 4; ++p) {
        const int f = p * 256 + tid;
        const int m = (int)row0 + (f >> 3);
        const long ri = gat ? (long)vidx[(long)bz * LL + m] : (long)m;
        aRow[p] = A + ri * lda + (f & 7) * 4;
        bRow[p] = B + (col0 + (f >> 3)) * ldb + (f & 7) * 4;
    }

    const int nIter = K >> 5;
    float4 rA[4], rB[4];

    auto load_tile = [&](int it) {
        const long ko = (long)it * 32;
#pragma unroll
        for (int p = 0; p < 4; ++p) rA[p] = *reinterpret_cast<const float4*>(aRow[p] + ko);
#pragma unroll
        for (int p = 0; p < 4; ++p) rB[p] = *reinterpret_cast<const float4*>(bRow[p] + ko);
    };

    auto store_tile = [&](uint16_t* st) {
#pragma unroll
        for (int p = 0; p < 4; ++p) {
            const int f = p * 256 + tid;
            {
                const int m = f >> 3, kc = (f & 7) * 4;
                float4 v = rA[p];
                uint32_t h0, l0, h1, l1;
                split2(v.x, v.y, h0, l0);
                split2(v.z, v.w, h1, l1);
                *reinterpret_cast<uint2*>(st + m * 40 + kc) = make_uint2(h0, h1);
            }
            {
                const int n = f >> 3, kc = (f & 7) * 4;
                float4 v = rB[p];
                uint32_t h0, l0, h1, l1;
                split2(v.x, v.y, h0, l0);
                split2(v.z, v.w, h1, l1);
                *reinterpret_cast<uint2*>(st + 10240 + n * 40 + kc) = make_uint2(h0, h1);
                *reinterpret_cast<uint2*>(st + 15360 + n * 40 + kc) = make_uint2(l0, l1);
            }
        }
    };

    float acc[4][4][4];
#pragma unroll
    for (int i = 0; i < 4; ++i)
#pragma unroll
        for (int j = 0; j < 4; ++j)
#pragma unroll
            for (int r = 0; r < 4; ++r) acc[i][j][r] = 0.0f;

    load_tile(0);
    store_tile(smh);
    __syncthreads();

    for (int it = 0; it < nIter; ++it) {
        const bool more = (it + 1 < nIter);
        if (more) load_tile(it + 1);

        const uint32_t* sw = reinterpret_cast<const uint32_t*>(smh + (it & 1) * STAGE_H);

#pragma unroll
        for (int ks = 0; ks < 2; ++ks) {
            uint32_t aH[4][4], bH[4][2], bL[4][2];
#pragma unroll
            for (int i = 0; i < 4; ++i) {
                const int r  = wm + i * 16 + grp;
                const int w0 = r * 20 + tig + 8 * ks;
                const int w1 = (r + 8) * 20 + tig + 8 * ks;
                aH[i][0] = sw[w0];     aH[i][1] = sw[w1];
                aH[i][2] = sw[w0 + 4]; aH[i][3] = sw[w1 + 4];
            }
#pragma unroll
            for (int j = 0; j < 4; ++j) {
                const int n  = wn + j * 8 + grp;
                const int w0 = 5120 + n * 20 + tig + 8 * ks;
                bH[j][0] = sw[w0];        bH[j][1] = sw[w0 + 4];
                bL[j][0] = sw[2560 + w0]; bL[j][1] = sw[2560 + w0 + 4];
            }
#pragma unroll
            for (int i = 0; i < 4; ++i)
#pragma unroll
                for (int j = 0; j < 4; ++j)
                    mma_fp16(acc[i][j], aH[i], bH[j]);
#pragma unroll
            for (int i = 0; i < 4; ++i)
#pragma unroll
                for (int j = 0; j < 4; ++j)
                    mma_fp16(acc[i][j], aH[i], bL[j]);
        }

        if (more) store_tile(smh + ((it + 1) & 1) * STAGE_H);
        __syncthreads();
    }

#pragma unroll
    for (int i = 0; i < 4; ++i) {
        const long r0 = row0 + wm + i * 16 + grp;
#pragma unroll
        for (int j = 0; j < 4; ++j) {
            const long gc = col0 + wn + j * 8 + tig * 2;
            *reinterpret_cast<float2*>(C + r0 * ldc + gc) =
                make_float2(acc[i][j][0], acc[i][j][1]);
            *reinterpret_cast<float2*>(C + (r0 + 8) * ldc + gc) =
                make_float2(acc[i][j][2], acc[i][j][3]);
        }
    }
}

// ---------------------------------------------------------------------------
// fp16 split NT GEMM for logits (2-term, compacted-column early exit).
// C[M,N] = scale * A[M,K] * B[N,K]^T
// ---------------------------------------------------------------------------
__global__ __launch_bounds__(256)
void logits_gemm_nt(const float* __restrict__ A, const float* __restrict__ B,
                    float* __restrict__ C,
                    int K, long lda, long ldb, long ldc,
                    long sA, long sB, long sC, float scale,
                    const int* __restrict__ LvArr)
{
    extern __shared__ __align__(16) uint16_t smh[];

    const int tid  = threadIdx.x;
    const int wid  = tid >> 5;
    const int lane = tid & 31;
    const int grp  = lane >> 2;
    const int tig  = lane & 3;
    const int wm   = (wid & 1) * 64;
    const int wn   = (wid >> 1) * 32;

    const int bz = blockIdx.z;
    const long row0 = (long)blockIdx.y * 128;
    const long col0 = (long)blockIdx.x * 128;

    if (col0 >= LvArr[bz]) return;

    A += (long)bz * sA;
    B += (long)bz * sB;
    C += (long)bz * sC;

    const float* aRow[4];
    const float* bRow[4];
#pragma unroll
    for (int p = 0; p < 4; ++p) {
        const int f = p * 256 + tid;
        aRow[p] = A + (row0 + (f >> 3)) * lda + (f & 7) * 4;
        bRow[p] = B + (col0 + (f >> 3)) * ldb + (f & 7) * 4;
    }

    const int nIter = K >> 5;
    float4 rA[4], rB[4];

    auto load_tile = [&](int it) {
        const long ko = (long)it * 32;
#pragma unroll
        for (int p = 0; p < 4; ++p) rA[p] = *reinterpret_cast<const float4*>(aRow[p] + ko);
#pragma unroll
        for (int p = 0; p < 4; ++p) rB[p] = *reinterpret_cast<const float4*>(bRow[p] + ko);
    };

    auto store_tile = [&](uint16_t* st) {
#pragma unroll
        for (int p = 0; p < 4; ++p) {
            const int f = p * 256 + tid;
            {
                const int m = f >> 3, kc = (f & 7) * 4;
                float4 v = rA[p];
                uint32_t h0, l0, h1, l1;
                split2(v.x, v.y, h0, l0);
                split2(v.z, v.w, h1, l1);
                *reinterpret_cast<uint2*>(st + m * 40 + kc) = make_uint2(h0, h1);
            }
            {
                const int n = f >> 3, kc = (f & 7) * 4;
                float4 v = rB[p];
                uint32_t h0, l0, h1, l1;
                split2(v.x, v.y, h0, l0);
                split2(v.z, v.w, h1, l1);
                *reinterpret_cast<uint2*>(st + 10240 + n * 40 + kc) = make_uint2(h0, h1);
                *reinterpret_cast<uint2*>(st + 15360 + n * 40 + kc) = make_uint2(l0, l1);
            }
        }
    };

    float acc[4][4][4];
#pragma unroll
    for (int i = 0; i < 4; ++i)
#pragma unroll
        for (int j = 0; j < 4; ++j)
#pragma unroll
            for (int r = 0; r < 4; ++r) acc[i][j][r] = 0.0f;

    load_tile(0);
    store_tile(smh);
    __syncthreads();

    for (int it = 0; it < nIter; ++it) {
        const bool more = (it + 1 < nIter);
        if (more) load_tile(it + 1);

        const uint32_t* sw = reinterpret_cast<const uint32_t*>(smh + (it & 1) * STAGE_H);

#pragma unroll
        for (int ks = 0; ks < 2; ++ks) {
            uint32_t aH[4][4], bH[4][2], bL[4][2];
#pragma unroll
            for (int i = 0; i < 4; ++i) {
                const int r  = wm + i * 16 + grp;
                const int w0 = r * 20 + tig + 8 * ks;
                const int w1 = (r + 8) * 20 + tig + 8 * ks;
                aH[i][0] = sw[w0];     aH[i][1] = sw[w1];
                aH[i][2] = sw[w0 + 4]; aH[i][3] = sw[w1 + 4];
            }
#pragma unroll
            for (int j = 0; j < 4; ++j) {
                const int n  = wn + j * 8 + grp;
                const int w0 = 5120 + n * 20 + tig + 8 * ks;
                bH[j][0] = sw[w0];        bH[j][1] = sw[w0 + 4];
                bL[j][0] = sw[2560 + w0]; bL[j][1] = sw[2560 + w0 + 4];
            }
#pragma unroll
            for (int i = 0; i < 4; ++i)
#pragma unroll
                for (int j = 0; j < 4; ++j)
                    mma_fp16(acc[i][j], aH[i], bH[j]);
#pragma unroll
            for (int i = 0; i < 4; ++i)
#pragma unroll
                for (int j = 0; j < 4; ++j)
                    mma_fp16(acc[i][j], aH[i], bL[j]);
        }

        if (more) store_tile(smh + ((it + 1) & 1) * STAGE_H);
        __syncthreads();
    }

#pragma unroll
    for (int i = 0; i < 4; ++i) {
        const long r0 = row0 + wm + i * 16 + grp;
#pragma unroll
        for (int j = 0; j < 4; ++j) {
            const long gc = col0 + wn + j * 8 + tig * 2;
            *reinterpret_cast<float2*>(C + r0 * ldc + gc) =
                make_float2(acc[i][j][0] * scale, acc[i][j][1] * scale);
            *reinterpret_cast<float2*>(C + (r0 + 8) * ldc + gc) =
                make_float2(acc[i][j][2] * scale, acc[i][j][3] * scale);
        }
    }
}

// ---------------------------------------------------------------------------
// Pure fp16 NN GEMM (Z = alpha_c * H_c), variable compacted K per batch.
// ---------------------------------------------------------------------------
#define ZSTAGE_H 9472
#define ZNSTAGE 3
#define SMEM_Z (ZNSTAGE * ZSTAGE_H * 2)   // 56832 bytes

__global__ __launch_bounds__(256)
void fp16_gemm_nn(const __half* __restrict__ A, const __half* __restrict__ B,
                  float* __restrict__ C,
                  long lda, long ldb, long ldc,
                  long sA, long sB, long sC, const int* __restrict__ LvArr)
{
    extern __shared__ __align__(16) __half smz[];

    const int tid  = threadIdx.x;
    const int wid  = tid >> 5;
    const int lane = tid & 31;
    const int grp  = lane >> 2;
    const int tig  = lane & 3;
    const int wm   = (wid & 1) * 64;
    const int wn   = (wid >> 1) * 32;

    const int bz = blockIdx.z;
    const int Lv = LvArr[bz];
    const int nIter = ((Lv + 127) & ~127) >> 5;

    A += (long)bz * sA;
    B += (long)bz * sB;
    C += (long)bz * sC;

    const long row0 = (long)blockIdx.y * 128;
    const long col0 = (long)blockIdx.x * 128;

    const uint32_t aoff = (uint32_t)((wm + (lane & 15)) * 40 + 8 * (lane >> 4));
    const uint32_t boff = (uint32_t)(5120 + (lane & 15) * 136 + wn + 8 * (lane >> 4));

    const uint32_t smz_base = (uint32_t)__cvta_generic_to_shared(smz);

    auto issue_stage = [&](int it) {
        __half* sa = smz + (it % ZNSTAGE) * ZSTAGE_H;
        __half* sb = sa + 5120;
        const __half* pA = A + row0 * lda + (long)it * 32;
#pragma unroll
        for (int p = 0; p < 2; ++p) {
            const int f = p * 256 + tid;
            const int m = f >> 2, kc = (f & 3) * 8;
            cp16(sa + m * 40 + kc, pA + (long)m * lda + kc);
        }
        const __half* pB = B + (long)it * 32 * ldb + col0;
#pragma unroll
        for (int p = 0; p < 2; ++p) {
            const int f = p * 256 + tid;
            const int k = f >> 4, nc = (f & 15) * 8;
            cp16(sb + k * 136 + nc, pB + (long)k * ldb + nc);
        }
    };

    float acc[4][4][4];
#pragma unroll
    for (int i = 0; i < 4; ++i)
#pragma unroll
        for (int j = 0; j < 4; ++j)
#pragma unroll
            for (int r = 0; r < 4; ++r) acc[i][j][r] = 0.0f;

    issue_stage(0); CP_COMMIT();
    issue_stage(1); CP_COMMIT();

    for (int it = 0; it < nIter; ++it) {
        CP_WAIT1();
        __syncthreads();

        if (it + 2 < nIter) issue_stage(it + 2);
        CP_COMMIT();

        const uint32_t stb = smz_base + (uint32_t)((it % ZNSTAGE) * ZSTAGE_H) * 2;

#pragma unroll
        for (int s = 0; s < 2; ++s) {
            uint32_t aF[4][4], bF[2][4];
#pragma unroll
            for (int i = 0; i < 4; ++i)
                ldsm_x4(aF[i], stb + (aoff + i * 16 * 40 + s * 16) * 2);
#pragma unroll
            for (int jp = 0; jp < 2; ++jp)
                ldsm_x4_t(bF[jp], stb + (boff + s * 16 * 136 + jp * 16) * 2);
#pragma unroll
            for (int i = 0; i < 4; ++i) {
#pragma unroll
                for (int jp = 0; jp < 2; ++jp) {
                    mma_fp16(acc[i][2 * jp + 0], aF[i], &bF[jp][0]);
                    mma_fp16(acc[i][2 * jp + 1], aF[i], &bF[jp][2]);
                }
            }
        }
        __syncthreads();
    }

#pragma unroll
    for (int i = 0; i < 4; ++i) {
        const long r0 = row0 + wm + i * 16 + grp;
#pragma unroll
        for (int j = 0; j < 4; ++j) {
            const long gc = col0 + wn + j * 8 + tig * 2;
            *reinterpret_cast<float2*>(C + r0 * ldc + gc) =
                make_float2(acc[i][j][0], acc[i][j][1]);
            *reinterpret_cast<float2*>(C + (r0 + 8) * ldc + gc) =
                make_float2(acc[i][j][2], acc[i][j][3]);
        }
    }
}

// ---------------------------------------------------------------------------
// Length-aware row softmax over compacted columns; fp16 alpha out (zero pad).
// ---------------------------------------------------------------------------
__global__ __launch_bounds__(256)
void softmax_kernel(const float* __restrict__ S, __half* __restrict__ Ah,
                    const int* __restrict__ LvArr)
{
    __shared__ float4 buf[LL / 4];
    __shared__ float red[256];

    const int tid = threadIdx.x;
    const int b = blockIdx.x >> 10;
    const int Lv = LvArr[b];
    const int L4 = ((Lv + 127) & ~127) >> 2;

    const float4* p = reinterpret_cast<const float4*>(S + (long)blockIdx.x * LL);
    uint2* out = reinterpret_cast<uint2*>(Ah + (long)blockIdx.x * LL);

    float m = -FLT_MAX;
    for (int i = tid; i < L4; i += 256) {
        float4 v = p[i];
        const int j = i * 4;
        if (j     >= Lv) v.x = -1e30f;
        if (j + 1 >= Lv) v.y = -1e30f;
        if (j + 2 >= Lv) v.z = -1e30f;
        if (j + 3 >= Lv) v.w = -1e30f;
        buf[i] = v;
        m = fmaxf(m, fmaxf(fmaxf(v.x, v.y), fmaxf(v.z, v.w)));
    }
    red[tid] = m;
    __syncthreads();
    for (int s = 128; s > 0; s >>= 1) {
        if (tid < s) red[tid] = fmaxf(red[tid], red[tid + s]);
        __syncthreads();
    }
    m = red[0];
    __syncthreads();

    float sum = 0.0f;
    for (int i = tid; i < L4; i += 256) {
        float4 v = buf[i];
        v.x = __expf(v.x - m); v.y = __expf(v.y - m);
        v.z = __expf(v.z - m); v.w = __expf(v.w - m);
        buf[i] = v;
        sum += v.x + v.y + v.z + v.w;
    }
    red[tid] = sum;
    __syncthreads();
    for (int s = 128; s > 0; s >>= 1) {
        if (tid < s) red[tid] += red[tid + s];
        __syncthreads();
    }
    const float inv = 1.0f / red[0];

    for (int i = tid; i < L4; i += 256) {
        float4 v = buf[i];
        uint2 o;
        o.x = h2_u32(__floats2half2_rn(v.x * inv, v.y * inv));
        o.y = h2_u32(__floats2half2_rn(v.z * inv, v.w * inv));
        out[i] = o;
    }
}

// ---------------------------------------------------------------------------
// Launch. Inputs: H [B,L,DH] f32, G [B,T,DG] f32, mask [B,L] int32,
// Wk_w [P,DH] f32, Wq_w [P,DG] f32. Output Z [B,T,DH] f32.
// ---------------------------------------------------------------------------
extern "C" void kernel_launch(void* const* d_in, const int* in_sizes, int n_in,
                              void* d_out, int out_size)
{
    const float* H    = (const float*)d_in[0];
    const float* G    = (const float*)d_in[1];
    const int*   mask = (const int*)d_in[2];
    const float* Wk   = (const float*)d_in[3];
    const float* Wq   = (const float*)d_in[4];
    float*       Z    = (float*)d_out;

    float  *gK, *gQ, *gS;
    __half *gAh, *gHh;
    int *gVidx, *gLv;
    cudaGetSymbolAddress((void**)&gK,   g_K);
    cudaGetSymbolAddress((void**)&gQ,   g_Q);
    cudaGetSymbolAddress((void**)&gS,   g_S);
    cudaGetSymbolAddress((void**)&gAh,  g_Ah);
    cudaGetSymbolAddress((void**)&gHh,  g_Hh);
    cudaGetSymbolAddress((void**)&gVidx, g_vidx);
    cudaGetSymbolAddress((void**)&gLv,  g_Lv);

    cudaFuncSetAttribute((const void*)fused_proj_kernel,
                         cudaFuncAttributeMaxDynamicSharedMemorySize, SMEM_GEMM);
    cudaFuncSetAttribute((const void*)logits_gemm_nt,
                         cudaFuncAttributeMaxDynamicSharedMemorySize, SMEM_GEMM);
    cudaFuncSetAttribute((const void*)fp16_gemm_nn,
                         cudaFuncAttributeMaxDynamicSharedMemorySize, SMEM_Z);

    // 0) build compacted valid-key index lists
    compact_kernel<<<BB, 1024>>>(mask, gVidx, gLv);

    // 1) FUSED: K-proj (z=0..3, gathered, 2-term) + Q-proj (z=4, 2-term)
    //    + H gather/fp16 convert (z=5). Fills the chip in ~1.7 waves.
    fused_proj_kernel<<<dim3(2, 32, 6), 256, SMEM_GEMM>>>(
        H, Wk, gK, G, Wq, gQ, gVidx, gLv, gHh);

    // 2) S = scale * Q * Kc^T over compacted columns (2-term)
    logits_gemm_nt<<<dim3(32, TTQ / 128, BB), 256, SMEM_GEMM>>>(
        gQ, gK, gS, PPQ, PPQ, PPQ, LL,
        (long)TTQ * PPQ, (long)LL * PPQ, (long)TTQ * LL, 0.0625f, gLv);

    // 3) length-aware softmax, emitting zero-padded fp16 alpha
    softmax_kernel<<<BB * TTQ, 256>>>(gS, gAh, gLv);

    // 4) Z = alpha_c * Hc over compacted K (pure fp16, variable nIter)
    fp16_gemm_nn<<<dim3(DHQ / 128, TTQ / 128, BB), 256, SMEM_Z>>>(
        gAh, gHh, Z, LL, DHQ, DHQ,
        (long)TTQ * LL, (long)LL * DHQ, (long)TTQ * DHQ, gLv);
}